// round 1
// baseline (speedup 1.0000x reference)
#include <cuda_runtime.h>
#include <math.h>

// Problem constants
constexpr int B_  = 2;
constexpr int T_  = 2048;
constexpr int C_  = 1024;
constexpr int H_  = 16;
constexpr int HD_ = 64;
constexpr int BH_ = B_ * H_;

// Scratch (device globals — no allocation allowed)
__device__ float g_q[BH_ * T_ * HD_];   // [B,H,T,HD]
__device__ float g_k[BH_ * T_ * HD_];
__device__ float g_v[BH_ * T_ * HD_];
__device__ float g_y[B_ * T_ * C_];     // attention output, [B,T,C]

// ----------------------------------------------------------------------------
// GEMM: C[M,N] = A[M,K] @ B[K,N] + bias[N]
// Tile 64x64, BK=16, 256 threads, 4x4 accumulator per thread.
// EPI=0: plain row-major store to Cout
// EPI=1: scatter into g_q/g_k/g_v with [B,H,T,HD] layout (QKV epilogue)
// A_FROM_Y: read A from g_y (proj GEMM) instead of the pointer argument.
// ----------------------------------------------------------------------------
template<int EPI, bool A_FROM_Y>
__global__ void __launch_bounds__(256) gemm_kernel(
    const float* __restrict__ A_in, const float* __restrict__ Bmat,
    const float* __restrict__ bias, float* __restrict__ Cout,
    int M, int N, int K)
{
    const float* __restrict__ A = A_FROM_Y ? (const float*)g_y : A_in;

    __shared__ float As[16][64];   // [k][m]
    __shared__ float Bs[16][64];   // [k][n]

    const int tid = threadIdx.x;
    const int tx = tid & 15;       // 0..15  (n direction)
    const int ty = tid >> 4;       // 0..15  (m direction)
    const int m0 = blockIdx.y * 64;
    const int n0 = blockIdx.x * 64;

    // A-tile loader: 64 rows x 16 cols, one float4 per thread
    const int la_row = tid >> 2;        // 0..63
    const int la_c4  = tid & 3;         // 0..3
    // B-tile loader: 16 rows x 64 cols, one float4 per thread
    const int lb_row = tid >> 4;        // 0..15
    const int lb_c4  = tid & 15;        // 0..15

    float acc[4][4];
    #pragma unroll
    for (int i = 0; i < 4; i++)
        #pragma unroll
        for (int j = 0; j < 4; j++) acc[i][j] = 0.f;

    for (int k0 = 0; k0 < K; k0 += 16) {
        float4 av = *(const float4*)&A[(size_t)(m0 + la_row) * K + k0 + la_c4 * 4];
        float4 bv = *(const float4*)&Bmat[(size_t)(k0 + lb_row) * N + n0 + lb_c4 * 4];

        As[la_c4 * 4 + 0][la_row] = av.x;
        As[la_c4 * 4 + 1][la_row] = av.y;
        As[la_c4 * 4 + 2][la_row] = av.z;
        As[la_c4 * 4 + 3][la_row] = av.w;
        *(float4*)&Bs[lb_row][lb_c4 * 4] = bv;
        __syncthreads();

        #pragma unroll
        for (int kk = 0; kk < 16; kk++) {
            float4 a = *(const float4*)&As[kk][ty * 4];
            float4 b = *(const float4*)&Bs[kk][tx * 4];
            float af[4] = {a.x, a.y, a.z, a.w};
            float bf[4] = {b.x, b.y, b.z, b.w};
            #pragma unroll
            for (int i = 0; i < 4; i++)
                #pragma unroll
                for (int j = 0; j < 4; j++)
                    acc[i][j] += af[i] * bf[j];
        }
        __syncthreads();
    }

    #pragma unroll
    for (int i = 0; i < 4; i++) {
        const int m = m0 + ty * 4 + i;
        #pragma unroll
        for (int j = 0; j < 4; j++) {
            const int n = n0 + tx * 4 + j;
            float val = acc[i][j] + bias[n];
            if (EPI == 0) {
                Cout[(size_t)m * N + n] = val;
            } else {
                // QKV scatter: m = b*T + t ; n selects {q,k,v}, head, dim
                const int b   = m / T_;
                const int t   = m % T_;
                const int sel = n / C_;
                const int r   = n % C_;
                const int h   = r / HD_;
                const int d   = r % HD_;
                float* dst = (sel == 0) ? g_q : (sel == 1) ? g_k : g_v;
                dst[(((size_t)b * H_ + h) * T_ + t) * HD_ + d] = val;
            }
        }
    }
}

// ----------------------------------------------------------------------------
// Flash-style causal attention (fp32).
// grid = (T/128, B*H), 128 threads; each thread owns one query row.
// Key/Value tiles of 32 rows staged in smem; S staged in smem (avoids a
// dynamically-indexed register array under partial unroll).
// scale = 1/sqrt(C) = 1/32 (module quirk: NOT 1/sqrt(head_dim)).
// ----------------------------------------------------------------------------
__global__ void __launch_bounds__(128) attn_kernel()
{
    __shared__ float Ks[32][64];
    __shared__ float Vs[32][64];
    __shared__ float Ss[32][128];   // S[j][thread]

    const int bh  = blockIdx.y;
    const int tid = threadIdx.x;
    const int qi  = blockIdx.x * 128 + tid;

    const float* __restrict__ qb = g_q + (size_t)bh * T_ * HD_;
    const float* __restrict__ kp = g_k + (size_t)bh * T_ * HD_;
    const float* __restrict__ vp = g_v + (size_t)bh * T_ * HD_;

    float qreg[64];
    #pragma unroll
    for (int d4 = 0; d4 < 16; d4++) {
        float4 t4 = *(const float4*)&qb[(size_t)qi * HD_ + d4 * 4];
        qreg[d4 * 4 + 0] = t4.x;
        qreg[d4 * 4 + 1] = t4.y;
        qreg[d4 * 4 + 2] = t4.z;
        qreg[d4 * 4 + 3] = t4.w;
    }

    float o[64];
    #pragma unroll
    for (int d = 0; d < 64; d++) o[d] = 0.f;
    float mx = -INFINITY, l = 0.f;
    const float scale = 0.03125f;  // 1/sqrt(1024)

    const int kend = blockIdx.x * 128 + 128;  // causal horizon for this q-block

    for (int k0 = 0; k0 < kend; k0 += 32) {
        // Cooperative tile load: 32x64 floats each = 512 float4, 128 threads
        #pragma unroll
        for (int r = 0; r < 4; r++) {
            const int idx = r * 128 + tid;      // float4 index 0..511
            const int row = idx >> 4;
            const int c4  = idx & 15;
            *(float4*)&Ks[row][c4 * 4] = *(const float4*)&kp[(size_t)(k0 + row) * HD_ + c4 * 4];
            *(float4*)&Vs[row][c4 * 4] = *(const float4*)&vp[(size_t)(k0 + row) * HD_ + c4 * 4];
        }
        __syncthreads();

        // Warp-uniform activity test (qi within a warp spans one aligned 32-range)
        if (k0 <= qi) {
            float smax = -INFINITY;
            #pragma unroll 4
            for (int j = 0; j < 32; j++) {
                float accd = 0.f;
                #pragma unroll
                for (int d4 = 0; d4 < 16; d4++) {
                    float4 kv = *(const float4*)&Ks[j][d4 * 4];
                    accd += qreg[d4 * 4 + 0] * kv.x;
                    accd += qreg[d4 * 4 + 1] * kv.y;
                    accd += qreg[d4 * 4 + 2] * kv.z;
                    accd += qreg[d4 * 4 + 3] * kv.w;
                }
                float s = (k0 + j <= qi) ? accd * scale : -INFINITY;
                Ss[j][tid] = s;
                smax = fmaxf(smax, s);
            }

            const float mnew = fmaxf(mx, smax);
            const float corr = (mx == -INFINITY) ? 0.f : __expf(mx - mnew);
            l *= corr;
            #pragma unroll
            for (int d = 0; d < 64; d++) o[d] *= corr;

            #pragma unroll 4
            for (int j = 0; j < 32; j++) {
                const float p = __expf(Ss[j][tid] - mnew);  // masked -> exp(-inf)=0
                l += p;
                #pragma unroll
                for (int d4 = 0; d4 < 16; d4++) {
                    float4 vv = *(const float4*)&Vs[j][d4 * 4];
                    o[d4 * 4 + 0] += p * vv.x;
                    o[d4 * 4 + 1] += p * vv.y;
                    o[d4 * 4 + 2] += p * vv.z;
                    o[d4 * 4 + 3] += p * vv.w;
                }
            }
            mx = mnew;
        }
        __syncthreads();
    }

    const float inv = 1.0f / l;   // diagonal key always present -> l > 0
    const int b = bh / H_;
    const int h = bh % H_;
    float* yp = &g_y[((size_t)(b * T_ + qi)) * C_ + h * HD_];
    #pragma unroll
    for (int d4 = 0; d4 < 16; d4++) {
        float4 t4 = make_float4(o[d4 * 4 + 0] * inv, o[d4 * 4 + 1] * inv,
                                o[d4 * 4 + 2] * inv, o[d4 * 4 + 3] * inv);
        *(float4*)&yp[d4 * 4] = t4;
    }
}

// ----------------------------------------------------------------------------
// Launch: QKV GEMM (+scatter) -> causal flash attention -> proj GEMM
// ----------------------------------------------------------------------------
extern "C" void kernel_launch(void* const* d_in, const int* in_sizes, int n_in,
                              void* d_out, int out_size)
{
    const float* x      = (const float*)d_in[0];
    const float* W_attn = (const float*)d_in[1];
    const float* b_attn = (const float*)d_in[2];
    const float* W_proj = (const float*)d_in[3];
    const float* b_proj = (const float*)d_in[4];
    float* out = (float*)d_out;

    // 1) c = x @ W_attn + b_attn, scattered into g_q/g_k/g_v [B,H,T,HD]
    {
        dim3 grid((3 * C_) / 64, (B_ * T_) / 64);   // (48, 64)
        gemm_kernel<1, false><<<grid, 256>>>(x, W_attn, b_attn, nullptr,
                                             B_ * T_, 3 * C_, C_);
    }
    // 2) causal attention -> g_y [B,T,C]
    {
        dim3 grid(T_ / 128, BH_);                   // (16, 32)
        attn_kernel<<<grid, 128>>>();
    }
    // 3) out = g_y @ W_proj + b_proj
    {
        dim3 grid(C_ / 64, (B_ * T_) / 64);         // (16, 64)
        gemm_kernel<0, true><<<grid, 256>>>(nullptr, W_proj, b_proj, out,
                                            B_ * T_, C_, C_);
    }
}

// round 3
// speedup vs baseline: 2.6994x; 2.6994x over previous
#include <cuda_runtime.h>
#include <cuda_bf16.h>
#include <math.h>
#include <stdint.h>

// Problem constants
constexpr int B_  = 2;
constexpr int T_  = 2048;
constexpr int C_  = 1024;
constexpr int H_  = 16;
constexpr int HD_ = 64;
constexpr int BH_ = B_ * H_;
constexpr int M_  = B_ * T_;     // 4096
constexpr int K_  = C_;          // 1024
constexpr int NQ_ = 3 * C_;      // 3072

// ---------------------------------------------------------------------------
// Device-global scratch
// ---------------------------------------------------------------------------
__device__ __nv_bfloat16 g_qh[BH_ * T_ * HD_], g_ql[BH_ * T_ * HD_];
__device__ __nv_bfloat16 g_kh[BH_ * T_ * HD_], g_kl[BH_ * T_ * HD_];
__device__ __nv_bfloat16 g_vh[BH_ * T_ * HD_], g_vl[BH_ * T_ * HD_];
__device__ __nv_bfloat16 g_yh[M_ * C_],        g_yl[M_ * C_];
__device__ __nv_bfloat16 g_xh[M_ * K_],        g_xl[M_ * K_];
__device__ __nv_bfloat16 g_wah[NQ_ * K_],      g_wal[NQ_ * K_];  // W_attn^T [N,K]
__device__ __nv_bfloat16 g_wph[C_ * K_],       g_wpl[C_ * K_];   // W_proj^T [N,K]

// ---------------------------------------------------------------------------
// PTX helpers (baseline ISA: ldmatrix + mma.sync, valid on compute_103)
// ---------------------------------------------------------------------------
__device__ __forceinline__ uint32_t su32(const void* p) {
    uint32_t a;
    asm("{ .reg .u64 t; cvta.to.shared.u64 t, %1; cvt.u32.u64 %0, t; }"
        : "=r"(a) : "l"(p));
    return a;
}

__device__ __forceinline__ void ldm_x4(uint32_t* r, uint32_t addr) {
    asm volatile("ldmatrix.sync.aligned.m8n8.x4.shared.b16 {%0,%1,%2,%3}, [%4];"
        : "=r"(r[0]), "=r"(r[1]), "=r"(r[2]), "=r"(r[3]) : "r"(addr));
}

__device__ __forceinline__ void ldm_x4t(uint32_t* r, uint32_t addr) {
    asm volatile("ldmatrix.sync.aligned.m8n8.x4.trans.shared.b16 {%0,%1,%2,%3}, [%4];"
        : "=r"(r[0]), "=r"(r[1]), "=r"(r[2]), "=r"(r[3]) : "r"(addr));
}

__device__ __forceinline__ void mma_bf16(float* d, const uint32_t* a,
                                         const uint32_t* b) {
    asm volatile(
        "mma.sync.aligned.m16n8k16.row.col.f32.bf16.bf16.f32 "
        "{%0,%1,%2,%3}, {%4,%5,%6,%7}, {%8,%9}, {%0,%1,%2,%3};"
        : "+f"(d[0]), "+f"(d[1]), "+f"(d[2]), "+f"(d[3])
        : "r"(a[0]), "r"(a[1]), "r"(a[2]), "r"(a[3]), "r"(b[0]), "r"(b[1]));
}

__device__ __forceinline__ void split1(float a, __nv_bfloat16& h, __nv_bfloat16& l) {
    h = __float2bfloat16_rn(a);
    l = __float2bfloat16_rn(a - __bfloat162float(h));
}
__device__ __forceinline__ uint32_t pack2(float a, float b) {
    __nv_bfloat162 t = __floats2bfloat162_rn(a, b);
    return *(uint32_t*)&t;
}

// ---------------------------------------------------------------------------
// Split x -> bf16 hi/lo
// ---------------------------------------------------------------------------
__global__ void __launch_bounds__(256) split_x(const float* __restrict__ src) {
    const int i = blockIdx.x * 256 + threadIdx.x;   // float4 index
    float4 v = ((const float4*)src)[i];
    __nv_bfloat16 h0, h1, h2, h3, l0, l1, l2, l3;
    split1(v.x, h0, l0); split1(v.y, h1, l1);
    split1(v.z, h2, l2); split1(v.w, h3, l3);
    ((__nv_bfloat162*)g_xh)[2 * i]     = __nv_bfloat162(h0, h1);
    ((__nv_bfloat162*)g_xh)[2 * i + 1] = __nv_bfloat162(h2, h3);
    ((__nv_bfloat162*)g_xl)[2 * i]     = __nv_bfloat162(l0, l1);
    ((__nv_bfloat162*)g_xl)[2 * i + 1] = __nv_bfloat162(l2, l3);
}

// Split + transpose weights: W[K,N] fp32 -> Wt[N,K] bf16 hi/lo
template<int DST>
__global__ void __launch_bounds__(256) split_wT(const float* __restrict__ W,
                                                int Kdim, int Ndim) {
    __nv_bfloat16* Th = (DST == 0) ? g_wah : g_wph;
    __nv_bfloat16* Tl = (DST == 0) ? g_wal : g_wpl;
    __shared__ float t[32][33];
    const int n0 = blockIdx.x * 32, k0 = blockIdx.y * 32;
    const int tx = threadIdx.x & 31, ty = threadIdx.x >> 5;
    #pragma unroll
    for (int r = 0; r < 32; r += 8)
        t[ty + r][tx] = W[(size_t)(k0 + ty + r) * Ndim + n0 + tx];
    __syncthreads();
    #pragma unroll
    for (int r = 0; r < 32; r += 8) {
        const int n = n0 + ty + r, k = k0 + tx;
        __nv_bfloat16 h, l;
        split1(t[tx][ty + r], h, l);
        Th[(size_t)n * Kdim + k] = h;
        Tl[(size_t)n * Kdim + k] = l;
    }
}

// ---------------------------------------------------------------------------
// HMMA GEMM: D = A[M,K] @ Wt[N,K]^T + bias, fp32 via bf16 hi/lo 3-term.
// 128x128 CTA tile, BK=32, 8 warps (2x4), warp tile 64x32.
// EPI=1: QKV -> scatter hi/lo into g_q*/g_k*/g_v*.  EPI=0: fp32 store.
// ---------------------------------------------------------------------------
constexpr int SST = 40;   // smem row stride (bf16) for 32-col tiles, pad 8

template<int EPI>
__global__ void __launch_bounds__(256) mma_gemm(
    const __nv_bfloat16* __restrict__ Ah, const __nv_bfloat16* __restrict__ Al,
    const __nv_bfloat16* __restrict__ Bh, const __nv_bfloat16* __restrict__ Bl,
    const float* __restrict__ bias, float* __restrict__ Cout, int N)
{
    __shared__ __nv_bfloat16 sAh[128 * SST], sAl[128 * SST];
    __shared__ __nv_bfloat16 sBh[128 * SST], sBl[128 * SST];

    const int tid = threadIdx.x;
    const int wid = tid >> 5, lane = tid & 31;
    const int wm = wid >> 2, wn = wid & 3;
    const int m0 = blockIdx.y * 128, n0 = blockIdx.x * 128;

    float acc[4][4][4] = {};

    for (int k0 = 0; k0 < K_; k0 += 32) {
        #pragma unroll
        for (int rr = 0; rr < 2; rr++) {
            const int idx = rr * 256 + tid;          // 0..511 uint4 slots
            const int row = idx >> 2;
            const int c8  = (idx & 3) * 8;
            const size_t ga = (size_t)(m0 + row) * K_ + k0 + c8;
            const size_t gb = (size_t)(n0 + row) * K_ + k0 + c8;
            *(uint4*)&sAh[row * SST + c8] = *(const uint4*)(Ah + ga);
            *(uint4*)&sAl[row * SST + c8] = *(const uint4*)(Al + ga);
            *(uint4*)&sBh[row * SST + c8] = *(const uint4*)(Bh + gb);
            *(uint4*)&sBl[row * SST + c8] = *(const uint4*)(Bl + gb);
        }
        __syncthreads();

        #pragma unroll
        for (int ks = 0; ks < 2; ks++) {
            uint32_t ah[4][4], al[4][4];
            const int arow = (lane & 15);
            const int acol = ks * 16 + ((lane >> 4) << 3);
            #pragma unroll
            for (int ti = 0; ti < 4; ti++) {
                const int off = (wm * 64 + ti * 16 + arow) * SST + acol;
                ldm_x4(ah[ti], su32(&sAh[off]));
                ldm_x4(al[ti], su32(&sAl[off]));
            }
            uint32_t bh4[2][4], bl4[2][4];
            const int brow = (lane & 7) + ((lane >> 4) << 3);
            const int bcol = ks * 16 + (((lane >> 3) & 1) << 3);
            #pragma unroll
            for (int tp = 0; tp < 2; tp++) {
                const int off = (wn * 32 + tp * 16 + brow) * SST + bcol;
                ldm_x4(bh4[tp], su32(&sBh[off]));
                ldm_x4(bl4[tp], su32(&sBl[off]));
            }
            #pragma unroll
            for (int ti = 0; ti < 4; ti++)
                #pragma unroll
                for (int tj = 0; tj < 4; tj++) {
                    const uint32_t* bhf = &bh4[tj >> 1][(tj & 1) * 2];
                    const uint32_t* blf = &bl4[tj >> 1][(tj & 1) * 2];
                    mma_bf16(acc[ti][tj], ah[ti], bhf);
                    mma_bf16(acc[ti][tj], ah[ti], blf);
                    mma_bf16(acc[ti][tj], al[ti], bhf);
                }
        }
        __syncthreads();
    }

    // Epilogue
    #pragma unroll
    for (int ti = 0; ti < 4; ti++) {
        #pragma unroll
        for (int tj = 0; tj < 4; tj++) {
            const int n = n0 + wn * 32 + tj * 8 + 2 * (lane & 3);
            const float b0 = bias[n], b1 = bias[n + 1];
            #pragma unroll
            for (int half = 0; half < 2; half++) {
                const int m = m0 + wm * 64 + ti * 16 + (lane >> 2) + half * 8;
                const float v0 = acc[ti][tj][half * 2 + 0] + b0;
                const float v1 = acc[ti][tj][half * 2 + 1] + b1;
                if (EPI == 0) {
                    float2* p = (float2*)&Cout[(size_t)m * N + n];
                    *p = make_float2(v0, v1);
                } else {
                    const int sel = n >> 10;
                    const int rr  = n & 1023;
                    const int h   = rr >> 6;
                    const int d   = rr & 63;
                    const int bb  = m >> 11;
                    const int t   = m & 2047;
                    const size_t o = (((size_t)bb * H_ + h) * T_ + t) * HD_ + d;
                    __nv_bfloat16 h0, l0, h1, l1;
                    split1(v0, h0, l0); split1(v1, h1, l1);
                    __nv_bfloat16* dh = (sel == 0) ? g_qh : (sel == 1) ? g_kh : g_vh;
                    __nv_bfloat16* dl = (sel == 0) ? g_ql : (sel == 1) ? g_kl : g_vl;
                    *(__nv_bfloat162*)(dh + o) = __nv_bfloat162(h0, h1);
                    *(__nv_bfloat162*)(dl + o) = __nv_bfloat162(l0, l1);
                }
            }
        }
    }
}

// ---------------------------------------------------------------------------
// Causal flash attention on HMMA. CTA = (bh, 64-query block), 4 warps x 16 rows.
// K/V tiles of 64 keys in smem (hi/lo). S and PV are 3-term hi/lo mmas.
// scale = 1/sqrt(C) = 1/32.
// ---------------------------------------------------------------------------
constexpr int AST = 72;   // smem row stride (bf16), 64 + 8 pad

__global__ void __launch_bounds__(128) attn_kernel() {
    __shared__ __nv_bfloat16 sKh[64 * AST], sKl[64 * AST];
    __shared__ __nv_bfloat16 sVh[64 * AST], sVl[64 * AST];

    const int bh  = blockIdx.y;
    const int q0  = blockIdx.x * 64;
    const int tid = threadIdx.x, wid = tid >> 5, lane = tid & 31;

    const size_t base = (size_t)bh * T_ * HD_;
    const __nv_bfloat16* __restrict__ qhp = g_qh + base;
    const __nv_bfloat16* __restrict__ qlp = g_ql + base;
    const __nv_bfloat16* __restrict__ khp = g_kh + base;
    const __nv_bfloat16* __restrict__ klp = g_kl + base;
    const __nv_bfloat16* __restrict__ vhp = g_vh + base;
    const __nv_bfloat16* __restrict__ vlp = g_vl + base;

    // Stage Q (hi in sKh, lo in sKl), pull A-fragments to registers.
    #pragma unroll
    for (int rr = 0; rr < 4; rr++) {
        const int idx = rr * 128 + tid;          // 512 uint4 slots
        const int row = idx >> 3, c8 = (idx & 7) * 8;
        const size_t g = (size_t)(q0 + row) * HD_ + c8;
        *(uint4*)&sKh[row * AST + c8] = *(const uint4*)(qhp + g);
        *(uint4*)&sKl[row * AST + c8] = *(const uint4*)(qlp + g);
    }
    __syncthreads();

    uint32_t qh[4][4], ql[4][4];
    {
        const int arow = lane & 15;
        const int ac   = (lane >> 4) << 3;
        #pragma unroll
        for (int dt = 0; dt < 4; dt++) {
            const int off = (wid * 16 + arow) * AST + dt * 16 + ac;
            ldm_x4(qh[dt], su32(&sKh[off]));
            ldm_x4(ql[dt], su32(&sKl[off]));
        }
    }
    __syncthreads();

    float of[8][4] = {};
    float m0r = -1e30f, m1r = -1e30f, l0r = 0.f, l1r = 0.f;
    const float scale = 0.03125f;

    for (int k0 = 0; k0 <= q0; k0 += 64) {
        // Load K/V hi/lo tiles
        #pragma unroll
        for (int rr = 0; rr < 4; rr++) {
            const int idx = rr * 128 + tid;
            const int row = idx >> 3, c8 = (idx & 7) * 8;
            const size_t g = (size_t)(k0 + row) * HD_ + c8;
            *(uint4*)&sKh[row * AST + c8] = *(const uint4*)(khp + g);
            *(uint4*)&sKl[row * AST + c8] = *(const uint4*)(klp + g);
            *(uint4*)&sVh[row * AST + c8] = *(const uint4*)(vhp + g);
            *(uint4*)&sVl[row * AST + c8] = *(const uint4*)(vlp + g);
        }
        __syncthreads();

        // S = Q K^T (3-term)
        float sf[8][4];
        const int krow = lane & 7;
        const int kc   = (lane >> 3) << 3;       // 0,8,16,24
        #pragma unroll
        for (int nt = 0; nt < 8; nt++) {
            sf[nt][0] = sf[nt][1] = sf[nt][2] = sf[nt][3] = 0.f;
            uint32_t kh0[4], kh1[4], kl0[4], kl1[4];
            const int off0 = (nt * 8 + krow) * AST + kc;
            const int off1 = off0 + 32;
            ldm_x4(kh0, su32(&sKh[off0]));
            ldm_x4(kh1, su32(&sKh[off1]));
            ldm_x4(kl0, su32(&sKl[off0]));
            ldm_x4(kl1, su32(&sKl[off1]));
            #pragma unroll
            for (int dt = 0; dt < 4; dt++) {
                const uint32_t* khf = (dt < 2) ? &kh0[(dt & 1) * 2] : &kh1[(dt & 1) * 2];
                const uint32_t* klf = (dt < 2) ? &kl0[(dt & 1) * 2] : &kl1[(dt & 1) * 2];
                mma_bf16(sf[nt], qh[dt], khf);
                mma_bf16(sf[nt], qh[dt], klf);
                mma_bf16(sf[nt], ql[dt], khf);
            }
        }

        // scale + causal mask (diagonal tile only)
        const int rr0 = wid * 16 + (lane >> 2);
        #pragma unroll
        for (int nt = 0; nt < 8; nt++) {
            #pragma unroll
            for (int e = 0; e < 4; e++) sf[nt][e] *= scale;
        }
        if (k0 == q0) {
            #pragma unroll
            for (int nt = 0; nt < 8; nt++) {
                const int col = nt * 8 + 2 * (lane & 3);
                #pragma unroll
                for (int e = 0; e < 4; e++) {
                    const int c = col + (e & 1);
                    const int r = rr0 + ((e >> 1) << 3);
                    if (c > r) sf[nt][e] = -1e30f;
                }
            }
        }

        // Online softmax stats
        float mt0 = -1e30f, mt1 = -1e30f;
        #pragma unroll
        for (int nt = 0; nt < 8; nt++) {
            mt0 = fmaxf(mt0, fmaxf(sf[nt][0], sf[nt][1]));
            mt1 = fmaxf(mt1, fmaxf(sf[nt][2], sf[nt][3]));
        }
        mt0 = fmaxf(mt0, __shfl_xor_sync(0xffffffff, mt0, 1));
        mt0 = fmaxf(mt0, __shfl_xor_sync(0xffffffff, mt0, 2));
        mt1 = fmaxf(mt1, __shfl_xor_sync(0xffffffff, mt1, 1));
        mt1 = fmaxf(mt1, __shfl_xor_sync(0xffffffff, mt1, 2));

        const float mn0 = fmaxf(m0r, mt0), mn1 = fmaxf(m1r, mt1);
        const float c0 = __expf(m0r - mn0), c1 = __expf(m1r - mn1);

        float ls0 = 0.f, ls1 = 0.f;
        #pragma unroll
        for (int nt = 0; nt < 8; nt++) {
            sf[nt][0] = __expf(sf[nt][0] - mn0);
            sf[nt][1] = __expf(sf[nt][1] - mn0);
            sf[nt][2] = __expf(sf[nt][2] - mn1);
            sf[nt][3] = __expf(sf[nt][3] - mn1);
            ls0 += sf[nt][0] + sf[nt][1];
            ls1 += sf[nt][2] + sf[nt][3];
        }
        ls0 += __shfl_xor_sync(0xffffffff, ls0, 1);
        ls0 += __shfl_xor_sync(0xffffffff, ls0, 2);
        ls1 += __shfl_xor_sync(0xffffffff, ls1, 1);
        ls1 += __shfl_xor_sync(0xffffffff, ls1, 2);

        l0r = l0r * c0 + ls0;
        l1r = l1r * c1 + ls1;
        m0r = mn0; m1r = mn1;

        #pragma unroll
        for (int nt = 0; nt < 8; nt++) {
            of[nt][0] *= c0; of[nt][1] *= c0;
            of[nt][2] *= c1; of[nt][3] *= c1;
        }

        // Pack P into A-fragments (hi/lo)
        uint32_t ph[4][4], pl[4][4];
        #pragma unroll
        for (int kt = 0; kt < 4; kt++) {
            #pragma unroll
            for (int q = 0; q < 4; q++) {
                const float a = sf[2 * kt + (q >> 1)][(q & 1) * 2 + 0];
                const float b = sf[2 * kt + (q >> 1)][(q & 1) * 2 + 1];
                __nv_bfloat16 ha, la, hb, lb;
                split1(a, ha, la); split1(b, hb, lb);
                ph[kt][q] = pack2(__bfloat162float(ha), __bfloat162float(hb));
                pl[kt][q] = pack2(__bfloat162float(la), __bfloat162float(lb));
            }
        }
        // A-frag order fix: a0a1=(row,kl), a2a3=(row+8,kl), a4a5=(row,kh), a6a7
        // sf[2kt] holds cols kl (c0c1 row, c2c3 row+8); sf[2kt+1] cols kh.
        // q mapping above: q0=sf[2kt][0,1](row,kl)=a0 ✓ q1=sf[2kt][2,3](row+8,kl)=a2→slot1 ✓
        // q2=sf[2kt+1][0,1](row,kh)=a4→slot2 ✓ q3=a6 ✓

        // O += P V (3-term)
        #pragma unroll
        for (int ntd = 0; ntd < 8; ntd++) {
            uint32_t vha[4], vhb[4], vla[4], vlb[4];
            const int offa = (lane)      * AST + ntd * 8;
            const int offb = (32 + lane) * AST + ntd * 8;
            ldm_x4t(vha, su32(&sVh[offa]));
            ldm_x4t(vhb, su32(&sVh[offb]));
            ldm_x4t(vla, su32(&sVl[offa]));
            ldm_x4t(vlb, su32(&sVl[offb]));
            #pragma unroll
            for (int kt = 0; kt < 4; kt++) {
                const uint32_t* vhf = (kt < 2) ? &vha[(kt & 1) * 2] : &vhb[(kt & 1) * 2];
                const uint32_t* vlf = (kt < 2) ? &vla[(kt & 1) * 2] : &vlb[(kt & 1) * 2];
                mma_bf16(of[ntd], ph[kt], vhf);
                mma_bf16(of[ntd], ph[kt], vlf);
                mma_bf16(of[ntd], pl[kt], vhf);
            }
        }
        __syncthreads();
    }

    // Normalize + store y as bf16 hi/lo (proj GEMM A operand)
    const float inv0 = 1.f / l0r, inv1 = 1.f / l1r;
    const int b = bh >> 4, h = bh & 15;
    const int row0 = q0 + wid * 16 + (lane >> 2);
    const int dx = 2 * (lane & 3);
    #pragma unroll
    for (int ntd = 0; ntd < 8; ntd++) {
        const int d = h * HD_ + ntd * 8 + dx;
        {
            const float y0 = of[ntd][0] * inv0, y1 = of[ntd][1] * inv0;
            __nv_bfloat16 h0, l0, h1, l1;
            split1(y0, h0, l0); split1(y1, h1, l1);
            const size_t o = ((size_t)b * T_ + row0) * C_ + d;
            *(__nv_bfloat162*)(g_yh + o) = __nv_bfloat162(h0, h1);
            *(__nv_bfloat162*)(g_yl + o) = __nv_bfloat162(l0, l1);
        }
        {
            const float y0 = of[ntd][2] * inv1, y1 = of[ntd][3] * inv1;
            __nv_bfloat16 h0, l0, h1, l1;
            split1(y0, h0, l0); split1(y1, h1, l1);
            const size_t o = ((size_t)b * T_ + row0 + 8) * C_ + d;
            *(__nv_bfloat162*)(g_yh + o) = __nv_bfloat162(h0, h1);
            *(__nv_bfloat162*)(g_yl + o) = __nv_bfloat162(l0, l1);
        }
    }
}

// ---------------------------------------------------------------------------
// Launch
// ---------------------------------------------------------------------------
extern "C" void kernel_launch(void* const* d_in, const int* in_sizes, int n_in,
                              void* d_out, int out_size)
{
    const float* x      = (const float*)d_in[0];
    const float* W_attn = (const float*)d_in[1];
    const float* b_attn = (const float*)d_in[2];
    const float* W_proj = (const float*)d_in[3];
    const float* b_proj = (const float*)d_in[4];
    float* out = (float*)d_out;

    __nv_bfloat16 *xh, *xl, *wah, *wal, *wph, *wpl, *yh, *yl;
    cudaGetSymbolAddress((void**)&xh,  g_xh);
    cudaGetSymbolAddress((void**)&xl,  g_xl);
    cudaGetSymbolAddress((void**)&wah, g_wah);
    cudaGetSymbolAddress((void**)&wal, g_wal);
    cudaGetSymbolAddress((void**)&wph, g_wph);
    cudaGetSymbolAddress((void**)&wpl, g_wpl);
    cudaGetSymbolAddress((void**)&yh,  g_yh);
    cudaGetSymbolAddress((void**)&yl,  g_yl);

    // 1) splits
    split_x<<<(M_ * K_) / 1024, 256>>>(x);
    split_wT<0><<<dim3(NQ_ / 32, K_ / 32), 256>>>(W_attn, K_, NQ_);
    split_wT<1><<<dim3(C_ / 32, K_ / 32), 256>>>(W_proj, K_, C_);

    // 2) QKV GEMM -> q/k/v hi/lo
    mma_gemm<1><<<dim3(NQ_ / 128, M_ / 128), 256>>>(xh, xl, wah, wal,
                                                    b_attn, nullptr, NQ_);
    // 3) causal attention -> y hi/lo
    attn_kernel<<<dim3(T_ / 64, BH_), 128>>>();

    // 4) proj GEMM -> out
    mma_gemm<0><<<dim3(C_ / 128, M_ / 128), 256>>>(yh, yl, wph, wpl,
                                                   b_proj, out, C_);
}

// round 4
// speedup vs baseline: 3.1080x; 1.1514x over previous
#include <cuda_runtime.h>
#include <cuda_bf16.h>
#include <math.h>
#include <stdint.h>

// Problem constants
constexpr int B_  = 2;
constexpr int T_  = 2048;
constexpr int C_  = 1024;
constexpr int H_  = 16;
constexpr int HD_ = 64;
constexpr int BH_ = B_ * H_;
constexpr int M_  = B_ * T_;     // 4096
constexpr int K_  = C_;          // 1024
constexpr int NQ_ = 3 * C_;      // 3072

// ---------------------------------------------------------------------------
// Device-global scratch
// ---------------------------------------------------------------------------
__device__ __nv_bfloat16 g_qh[BH_ * T_ * HD_], g_ql[BH_ * T_ * HD_];
__device__ __nv_bfloat16 g_kh[BH_ * T_ * HD_], g_kl[BH_ * T_ * HD_];
__device__ __nv_bfloat16 g_vh[BH_ * T_ * HD_], g_vl[BH_ * T_ * HD_];
__device__ __nv_bfloat16 g_yh[M_ * C_],        g_yl[M_ * C_];
__device__ __nv_bfloat16 g_xh[M_ * K_],        g_xl[M_ * K_];
__device__ __nv_bfloat16 g_wah[NQ_ * K_],      g_wal[NQ_ * K_];  // W_attn^T [N,K]
__device__ __nv_bfloat16 g_wph[C_ * K_],       g_wpl[C_ * K_];   // W_proj^T [N,K]

// ---------------------------------------------------------------------------
// PTX helpers (baseline ISA features only)
// ---------------------------------------------------------------------------
__device__ __forceinline__ uint32_t su32(const void* p) {
    uint32_t a;
    asm("{ .reg .u64 t; cvta.to.shared.u64 t, %1; cvt.u32.u64 %0, t; }"
        : "=r"(a) : "l"(p));
    return a;
}

__device__ __forceinline__ void ldm_x4(uint32_t* r, uint32_t addr) {
    asm volatile("ldmatrix.sync.aligned.m8n8.x4.shared.b16 {%0,%1,%2,%3}, [%4];"
        : "=r"(r[0]), "=r"(r[1]), "=r"(r[2]), "=r"(r[3]) : "r"(addr));
}

__device__ __forceinline__ void ldm_x4t(uint32_t* r, uint32_t addr) {
    asm volatile("ldmatrix.sync.aligned.m8n8.x4.trans.shared.b16 {%0,%1,%2,%3}, [%4];"
        : "=r"(r[0]), "=r"(r[1]), "=r"(r[2]), "=r"(r[3]) : "r"(addr));
}

__device__ __forceinline__ void mma_bf16(float* d, const uint32_t* a,
                                         const uint32_t* b) {
    asm volatile(
        "mma.sync.aligned.m16n8k16.row.col.f32.bf16.bf16.f32 "
        "{%0,%1,%2,%3}, {%4,%5,%6,%7}, {%8,%9}, {%0,%1,%2,%3};"
        : "+f"(d[0]), "+f"(d[1]), "+f"(d[2]), "+f"(d[3])
        : "r"(a[0]), "r"(a[1]), "r"(a[2]), "r"(a[3]), "r"(b[0]), "r"(b[1]));
}

__device__ __forceinline__ void cp16(uint32_t saddr, const void* g) {
    asm volatile("cp.async.cg.shared.global [%0], [%1], 16;"
                 :: "r"(saddr), "l"(g));
}
#define CP_COMMIT() asm volatile("cp.async.commit_group;" ::: "memory")
template<int N> __device__ __forceinline__ void cp_wait() {
    asm volatile("cp.async.wait_group %0;" :: "n"(N) : "memory");
}

__device__ __forceinline__ void split1(float a, __nv_bfloat16& h, __nv_bfloat16& l) {
    h = __float2bfloat16_rn(a);
    l = __float2bfloat16_rn(a - __bfloat162float(h));
}
__device__ __forceinline__ uint32_t pack2(float a, float b) {
    __nv_bfloat162 t = __floats2bfloat162_rn(a, b);
    return *(uint32_t*)&t;
}

// ---------------------------------------------------------------------------
// Split x -> bf16 hi/lo
// ---------------------------------------------------------------------------
__global__ void __launch_bounds__(256) split_x(const float* __restrict__ src) {
    const int i = blockIdx.x * 256 + threadIdx.x;   // float4 index
    float4 v = ((const float4*)src)[i];
    __nv_bfloat16 h0, h1, h2, h3, l0, l1, l2, l3;
    split1(v.x, h0, l0); split1(v.y, h1, l1);
    split1(v.z, h2, l2); split1(v.w, h3, l3);
    ((__nv_bfloat162*)g_xh)[2 * i]     = __nv_bfloat162(h0, h1);
    ((__nv_bfloat162*)g_xh)[2 * i + 1] = __nv_bfloat162(h2, h3);
    ((__nv_bfloat162*)g_xl)[2 * i]     = __nv_bfloat162(l0, l1);
    ((__nv_bfloat162*)g_xl)[2 * i + 1] = __nv_bfloat162(l2, l3);
}

// Split + transpose weights: W[K,N] fp32 -> Wt[N,K] bf16 hi/lo
template<int DST>
__global__ void __launch_bounds__(256) split_wT(const float* __restrict__ W,
                                                int Kdim, int Ndim) {
    __nv_bfloat16* Th = (DST == 0) ? g_wah : g_wph;
    __nv_bfloat16* Tl = (DST == 0) ? g_wal : g_wpl;
    __shared__ float t[32][33];
    const int n0 = blockIdx.x * 32, k0 = blockIdx.y * 32;
    const int tx = threadIdx.x & 31, ty = threadIdx.x >> 5;
    #pragma unroll
    for (int r = 0; r < 32; r += 8)
        t[ty + r][tx] = W[(size_t)(k0 + ty + r) * Ndim + n0 + tx];
    __syncthreads();
    #pragma unroll
    for (int r = 0; r < 32; r += 8) {
        const int n = n0 + ty + r, k = k0 + tx;
        __nv_bfloat16 h, l;
        split1(t[tx][ty + r], h, l);
        Th[(size_t)n * Kdim + k] = h;
        Tl[(size_t)n * Kdim + k] = l;
    }
}

// ---------------------------------------------------------------------------
// HMMA GEMM, cp.async double-buffered. 128x128 CTA, BK=64, 8 warps (2x4).
// 3-term bf16 hi/lo. EPI=1: QKV scatter (hi/lo).  EPI=0: fp32 store.
// ---------------------------------------------------------------------------
constexpr int GST    = 72;                 // smem row stride (bf16), 64+8 pad
constexpr int GTILE  = 128 * GST;          // bf16 per tile
constexpr int GSTAGE = 4 * GTILE;          // Ah,Al,Bh,Bl
constexpr int GSMEM  = 2 * GSTAGE * 2;     // bytes (2 stages) = 147456
constexpr int GNK    = K_ / 64;            // 16 k-chunks

template<int EPI>
__global__ void __launch_bounds__(256, 1) mma_gemm(
    const __nv_bfloat16* __restrict__ Ah, const __nv_bfloat16* __restrict__ Al,
    const __nv_bfloat16* __restrict__ Bh, const __nv_bfloat16* __restrict__ Bl,
    const float* __restrict__ bias, float* __restrict__ Cout, int N)
{
    extern __shared__ __nv_bfloat16 dsm[];

    const int tid = threadIdx.x;
    const int wid = tid >> 5, lane = tid & 31;
    const int wm = wid >> 2, wn = wid & 3;
    const int m0 = blockIdx.y * 128, n0 = blockIdx.x * 128;

    float acc[4][4][4] = {};

    // ---- stage issue: 4 tiles x 128 rows x 8 uint4 = 4096 cp16, 16/thread
    auto issue = [&](int kt, int stg) {
        const int k0 = kt * 64;
        __nv_bfloat16* s = dsm + stg * GSTAGE;
        #pragma unroll
        for (int it = 0; it < 16; it++) {
            const int idx  = it * 256 + tid;
            const int tile = idx >> 10;
            const int rem  = idx & 1023;
            const int row  = rem >> 3;
            const int c8   = (rem & 7) * 8;
            const __nv_bfloat16* gp;
            if      (tile == 0) gp = Ah + (size_t)(m0 + row) * K_ + k0 + c8;
            else if (tile == 1) gp = Al + (size_t)(m0 + row) * K_ + k0 + c8;
            else if (tile == 2) gp = Bh + (size_t)(n0 + row) * K_ + k0 + c8;
            else                gp = Bl + (size_t)(n0 + row) * K_ + k0 + c8;
            cp16(su32(&s[tile * GTILE + row * GST + c8]), gp);
        }
    };

    auto compute = [&](int stg) {
        const __nv_bfloat16* sAh = dsm + stg * GSTAGE;
        const __nv_bfloat16* sAl = sAh + GTILE;
        const __nv_bfloat16* sBh = sAl + GTILE;
        const __nv_bfloat16* sBl = sBh + GTILE;
        #pragma unroll
        for (int ks = 0; ks < 4; ks++) {
            uint32_t ah[4][4], al[4][4];
            const int arow = (lane & 15);
            const int acol = ks * 16 + ((lane >> 4) << 3);
            #pragma unroll
            for (int ti = 0; ti < 4; ti++) {
                const int off = (wm * 64 + ti * 16 + arow) * GST + acol;
                ldm_x4(ah[ti], su32(&sAh[off]));
                ldm_x4(al[ti], su32(&sAl[off]));
            }
            uint32_t bh4[2][4], bl4[2][4];
            const int brow = (lane & 7) + ((lane >> 4) << 3);
            const int bcol = ks * 16 + (((lane >> 3) & 1) << 3);
            #pragma unroll
            for (int tp = 0; tp < 2; tp++) {
                const int off = (wn * 32 + tp * 16 + brow) * GST + bcol;
                ldm_x4(bh4[tp], su32(&sBh[off]));
                ldm_x4(bl4[tp], su32(&sBl[off]));
            }
            #pragma unroll
            for (int ti = 0; ti < 4; ti++)
                #pragma unroll
                for (int tj = 0; tj < 4; tj++) {
                    const uint32_t* bhf = &bh4[tj >> 1][(tj & 1) * 2];
                    const uint32_t* blf = &bl4[tj >> 1][(tj & 1) * 2];
                    mma_bf16(acc[ti][tj], ah[ti], bhf);
                    mma_bf16(acc[ti][tj], ah[ti], blf);
                    mma_bf16(acc[ti][tj], al[ti], bhf);
                }
        }
    };

    issue(0, 0);
    CP_COMMIT();
    #pragma unroll 1
    for (int kt = 0; kt < GNK; kt++) {
        if (kt + 1 < GNK) {
            issue(kt + 1, (kt + 1) & 1);
            CP_COMMIT();
            cp_wait<1>();
        } else {
            cp_wait<0>();
        }
        __syncthreads();
        compute(kt & 1);
        __syncthreads();
    }

    // Epilogue
    #pragma unroll
    for (int ti = 0; ti < 4; ti++) {
        #pragma unroll
        for (int tj = 0; tj < 4; tj++) {
            const int n = n0 + wn * 32 + tj * 8 + 2 * (lane & 3);
            const float b0 = bias[n], b1 = bias[n + 1];
            #pragma unroll
            for (int half = 0; half < 2; half++) {
                const int m = m0 + wm * 64 + ti * 16 + (lane >> 2) + half * 8;
                const float v0 = acc[ti][tj][half * 2 + 0] + b0;
                const float v1 = acc[ti][tj][half * 2 + 1] + b1;
                if (EPI == 0) {
                    float2* p = (float2*)&Cout[(size_t)m * N + n];
                    *p = make_float2(v0, v1);
                } else {
                    const int sel = n >> 10;
                    const int rr  = n & 1023;
                    const int h   = rr >> 6;
                    const int d   = rr & 63;
                    const int bb  = m >> 11;
                    const int t   = m & 2047;
                    const size_t o = (((size_t)bb * H_ + h) * T_ + t) * HD_ + d;
                    __nv_bfloat16 h0, l0, h1, l1;
                    split1(v0, h0, l0); split1(v1, h1, l1);
                    __nv_bfloat16* dh = (sel == 0) ? g_qh : (sel == 1) ? g_kh : g_vh;
                    __nv_bfloat16* dl = (sel == 0) ? g_ql : (sel == 1) ? g_kl : g_vl;
                    *(__nv_bfloat162*)(dh + o) = __nv_bfloat162(h0, h1);
                    *(__nv_bfloat162*)(dl + o) = __nv_bfloat162(l0, l1);
                }
            }
        }
    }
}

// ---------------------------------------------------------------------------
// Causal flash attention on HMMA, cp.async double-buffered K/V tiles.
// CTA = 64 queries, 4 warps x 16 rows; 64-key tiles; 3-term hi/lo mmas.
// ---------------------------------------------------------------------------
constexpr int AST    = 72;               // row stride (bf16)
constexpr int ATILE  = 64 * AST;         // bf16 per tile
constexpr int ASTAGE = 4 * ATILE;        // Kh,Kl,Vh,Vl
constexpr int ASMEM  = 2 * ASTAGE * 2;   // bytes = 73728

__global__ void __launch_bounds__(128) attn_kernel() {
    extern __shared__ __nv_bfloat16 adsm[];

    const int bh  = blockIdx.y;
    const int q0  = blockIdx.x * 64;
    const int tid = threadIdx.x, wid = tid >> 5, lane = tid & 31;
    const int NT  = q0 / 64 + 1;

    const size_t base = (size_t)bh * T_ * HD_;
    const __nv_bfloat16* __restrict__ qhp = g_qh + base;
    const __nv_bfloat16* __restrict__ qlp = g_ql + base;
    const __nv_bfloat16* __restrict__ khp = g_kh + base;
    const __nv_bfloat16* __restrict__ klp = g_kl + base;
    const __nv_bfloat16* __restrict__ vhp = g_vh + base;
    const __nv_bfloat16* __restrict__ vlp = g_vl + base;

    // Stage Q into stage-0 Kh/Kl area, pull A-fragments, then release.
    {
        __nv_bfloat16* sQh = adsm;
        __nv_bfloat16* sQl = adsm + ATILE;
        #pragma unroll
        for (int rr = 0; rr < 4; rr++) {
            const int idx = rr * 128 + tid;          // 512 uint4 slots
            const int row = idx >> 3, c8 = (idx & 7) * 8;
            const size_t g = (size_t)(q0 + row) * HD_ + c8;
            *(uint4*)&sQh[row * AST + c8] = *(const uint4*)(qhp + g);
            *(uint4*)&sQl[row * AST + c8] = *(const uint4*)(qlp + g);
        }
    }
    __syncthreads();

    uint32_t qh[4][4], ql[4][4];
    {
        const int arow = lane & 15;
        const int ac   = (lane >> 4) << 3;
        #pragma unroll
        for (int dt = 0; dt < 4; dt++) {
            const int off = (wid * 16 + arow) * AST + dt * 16 + ac;
            ldm_x4(qh[dt], su32(&adsm[off]));
            ldm_x4(ql[dt], su32(&adsm[ATILE + off]));
        }
    }
    __syncthreads();

    auto issue_kv = [&](int t, int stg) {
        const int k0 = t * 64;
        __nv_bfloat16* s = adsm + stg * ASTAGE;
        #pragma unroll
        for (int it = 0; it < 16; it++) {
            const int idx  = it * 128 + tid;         // 2048 uint4 slots
            const int tile = idx >> 9;
            const int rem  = idx & 511;
            const int row  = rem >> 3;
            const int c8   = (rem & 7) * 8;
            const size_t g = (size_t)(k0 + row) * HD_ + c8;
            const __nv_bfloat16* gp;
            if      (tile == 0) gp = khp + g;
            else if (tile == 1) gp = klp + g;
            else if (tile == 2) gp = vhp + g;
            else                gp = vlp + g;
            cp16(su32(&s[tile * ATILE + row * AST + c8]), gp);
        }
    };

    float of[8][4] = {};
    float m0r = -1e30f, m1r = -1e30f, l0r = 0.f, l1r = 0.f;
    const float scale = 0.03125f;   // 1/sqrt(1024)

    issue_kv(0, 0);
    CP_COMMIT();

    #pragma unroll 1
    for (int t = 0; t < NT; t++) {
        if (t + 1 < NT) {
            issue_kv(t + 1, (t + 1) & 1);
            CP_COMMIT();
            cp_wait<1>();
        } else {
            cp_wait<0>();
        }
        __syncthreads();

        const __nv_bfloat16* sKh = adsm + (t & 1) * ASTAGE;
        const __nv_bfloat16* sKl = sKh + ATILE;
        const __nv_bfloat16* sVh = sKl + ATILE;
        const __nv_bfloat16* sVl = sVh + ATILE;
        const int k0 = t * 64;

        // S = Q K^T (3-term)
        float sf[8][4];
        const int krow = lane & 7;
        const int kc   = (lane >> 3) << 3;
        #pragma unroll
        for (int nt = 0; nt < 8; nt++) {
            sf[nt][0] = sf[nt][1] = sf[nt][2] = sf[nt][3] = 0.f;
            uint32_t kh0[4], kh1[4], kl0[4], kl1[4];
            const int off0 = (nt * 8 + krow) * AST + kc;
            const int off1 = off0 + 32;
            ldm_x4(kh0, su32(&sKh[off0]));
            ldm_x4(kh1, su32(&sKh[off1]));
            ldm_x4(kl0, su32(&sKl[off0]));
            ldm_x4(kl1, su32(&sKl[off1]));
            #pragma unroll
            for (int dt = 0; dt < 4; dt++) {
                const uint32_t* khf = (dt < 2) ? &kh0[(dt & 1) * 2] : &kh1[(dt & 1) * 2];
                const uint32_t* klf = (dt < 2) ? &kl0[(dt & 1) * 2] : &kl1[(dt & 1) * 2];
                mma_bf16(sf[nt], qh[dt], khf);
                mma_bf16(sf[nt], qh[dt], klf);
                mma_bf16(sf[nt], ql[dt], khf);
            }
        }

        // scale + causal mask (diagonal tile only)
        const int rr0 = wid * 16 + (lane >> 2);
        #pragma unroll
        for (int nt = 0; nt < 8; nt++) {
            #pragma unroll
            for (int e = 0; e < 4; e++) sf[nt][e] *= scale;
        }
        if (k0 == q0) {
            #pragma unroll
            for (int nt = 0; nt < 8; nt++) {
                const int col = nt * 8 + 2 * (lane & 3);
                #pragma unroll
                for (int e = 0; e < 4; e++) {
                    const int c = col + (e & 1);
                    const int r = rr0 + ((e >> 1) << 3);
                    if (c > r) sf[nt][e] = -1e30f;
                }
            }
        }

        // Online softmax stats
        float mt0 = -1e30f, mt1 = -1e30f;
        #pragma unroll
        for (int nt = 0; nt < 8; nt++) {
            mt0 = fmaxf(mt0, fmaxf(sf[nt][0], sf[nt][1]));
            mt1 = fmaxf(mt1, fmaxf(sf[nt][2], sf[nt][3]));
        }
        mt0 = fmaxf(mt0, __shfl_xor_sync(0xffffffff, mt0, 1));
        mt0 = fmaxf(mt0, __shfl_xor_sync(0xffffffff, mt0, 2));
        mt1 = fmaxf(mt1, __shfl_xor_sync(0xffffffff, mt1, 1));
        mt1 = fmaxf(mt1, __shfl_xor_sync(0xffffffff, mt1, 2));

        const float mn0 = fmaxf(m0r, mt0), mn1 = fmaxf(m1r, mt1);
        const float c0 = __expf(m0r - mn0), c1 = __expf(m1r - mn1);

        float ls0 = 0.f, ls1 = 0.f;
        #pragma unroll
        for (int nt = 0; nt < 8; nt++) {
            sf[nt][0] = __expf(sf[nt][0] - mn0);
            sf[nt][1] = __expf(sf[nt][1] - mn0);
            sf[nt][2] = __expf(sf[nt][2] - mn1);
            sf[nt][3] = __expf(sf[nt][3] - mn1);
            ls0 += sf[nt][0] + sf[nt][1];
            ls1 += sf[nt][2] + sf[nt][3];
        }
        ls0 += __shfl_xor_sync(0xffffffff, ls0, 1);
        ls0 += __shfl_xor_sync(0xffffffff, ls0, 2);
        ls1 += __shfl_xor_sync(0xffffffff, ls1, 1);
        ls1 += __shfl_xor_sync(0xffffffff, ls1, 2);

        l0r = l0r * c0 + ls0;
        l1r = l1r * c1 + ls1;
        m0r = mn0; m1r = mn1;

        #pragma unroll
        for (int nt = 0; nt < 8; nt++) {
            of[nt][0] *= c0; of[nt][1] *= c0;
            of[nt][2] *= c1; of[nt][3] *= c1;
        }

        // Pack P into A-fragments (hi/lo)
        uint32_t ph[4][4], pl[4][4];
        #pragma unroll
        for (int kt = 0; kt < 4; kt++) {
            #pragma unroll
            for (int q = 0; q < 4; q++) {
                const float a = sf[2 * kt + (q >> 1)][(q & 1) * 2 + 0];
                const float b = sf[2 * kt + (q >> 1)][(q & 1) * 2 + 1];
                __nv_bfloat16 ha, la, hb, lb;
                split1(a, ha, la); split1(b, hb, lb);
                ph[kt][q] = pack2(__bfloat162float(ha), __bfloat162float(hb));
                pl[kt][q] = pack2(__bfloat162float(la), __bfloat162float(lb));
            }
        }

        // O += P V (3-term)
        #pragma unroll
        for (int ntd = 0; ntd < 8; ntd++) {
            uint32_t vha[4], vhb[4], vla[4], vlb[4];
            const int offa = (lane)      * AST + ntd * 8;
            const int offb = (32 + lane) * AST + ntd * 8;
            ldm_x4t(vha, su32(&sVh[offa]));
            ldm_x4t(vhb, su32(&sVh[offb]));
            ldm_x4t(vla, su32(&sVl[offa]));
            ldm_x4t(vlb, su32(&sVl[offb]));
            #pragma unroll
            for (int kt = 0; kt < 4; kt++) {
                const uint32_t* vhf = (kt < 2) ? &vha[(kt & 1) * 2] : &vhb[(kt & 1) * 2];
                const uint32_t* vlf = (kt < 2) ? &vla[(kt & 1) * 2] : &vlb[(kt & 1) * 2];
                mma_bf16(of[ntd], ph[kt], vhf);
                mma_bf16(of[ntd], ph[kt], vlf);
                mma_bf16(of[ntd], pl[kt], vhf);
            }
        }
        __syncthreads();
    }

    // Normalize + store y as bf16 hi/lo (proj GEMM A operand)
    const float inv0 = 1.f / l0r, inv1 = 1.f / l1r;
    const int b = bh >> 4, h = bh & 15;
    const int row0 = q0 + wid * 16 + (lane >> 2);
    const int dx = 2 * (lane & 3);
    #pragma unroll
    for (int ntd = 0; ntd < 8; ntd++) {
        const int d = h * HD_ + ntd * 8 + dx;
        {
            const float y0 = of[ntd][0] * inv0, y1 = of[ntd][1] * inv0;
            __nv_bfloat16 h0, l0, h1, l1;
            split1(y0, h0, l0); split1(y1, h1, l1);
            const size_t o = ((size_t)b * T_ + row0) * C_ + d;
            *(__nv_bfloat162*)(g_yh + o) = __nv_bfloat162(h0, h1);
            *(__nv_bfloat162*)(g_yl + o) = __nv_bfloat162(l0, l1);
        }
        {
            const float y0 = of[ntd][2] * inv1, y1 = of[ntd][3] * inv1;
            __nv_bfloat16 h0, l0, h1, l1;
            split1(y0, h0, l0); split1(y1, h1, l1);
            const size_t o = ((size_t)b * T_ + row0 + 8) * C_ + d;
            *(__nv_bfloat162*)(g_yh + o) = __nv_bfloat162(h0, h1);
            *(__nv_bfloat162*)(g_yl + o) = __nv_bfloat162(l0, l1);
        }
    }
}

// ---------------------------------------------------------------------------
// Launch
// ---------------------------------------------------------------------------
extern "C" void kernel_launch(void* const* d_in, const int* in_sizes, int n_in,
                              void* d_out, int out_size)
{
    const float* x      = (const float*)d_in[0];
    const float* W_attn = (const float*)d_in[1];
    const float* b_attn = (const float*)d_in[2];
    const float* W_proj = (const float*)d_in[3];
    const float* b_proj = (const float*)d_in[4];
    float* out = (float*)d_out;

    __nv_bfloat16 *xh, *xl, *wah, *wal, *wph, *wpl, *yh, *yl;
    cudaGetSymbolAddress((void**)&xh,  g_xh);
    cudaGetSymbolAddress((void**)&xl,  g_xl);
    cudaGetSymbolAddress((void**)&wah, g_wah);
    cudaGetSymbolAddress((void**)&wal, g_wal);
    cudaGetSymbolAddress((void**)&wph, g_wph);
    cudaGetSymbolAddress((void**)&wpl, g_wpl);
    cudaGetSymbolAddress((void**)&yh,  g_yh);
    cudaGetSymbolAddress((void**)&yl,  g_yl);

    cudaFuncSetAttribute(mma_gemm<1>, cudaFuncAttributeMaxDynamicSharedMemorySize, GSMEM);
    cudaFuncSetAttribute(mma_gemm<0>, cudaFuncAttributeMaxDynamicSharedMemorySize, GSMEM);
    cudaFuncSetAttribute(attn_kernel, cudaFuncAttributeMaxDynamicSharedMemorySize, ASMEM);

    // 1) splits
    split_x<<<(M_ * K_) / 1024, 256>>>(x);
    split_wT<0><<<dim3(NQ_ / 32, K_ / 32), 256>>>(W_attn, K_, NQ_);
    split_wT<1><<<dim3(C_ / 32, K_ / 32), 256>>>(W_proj, K_, C_);

    // 2) QKV GEMM -> q/k/v hi/lo
    mma_gemm<1><<<dim3(NQ_ / 128, M_ / 128), 256, GSMEM>>>(xh, xl, wah, wal,
                                                           b_attn, nullptr, NQ_);
    // 3) causal attention -> y hi/lo
    attn_kernel<<<dim3(T_ / 64, BH_), 128, ASMEM>>>();

    // 4) proj GEMM -> out
    mma_gemm<0><<<dim3(C_ / 128, M_ / 128), 256, GSMEM>>>(yh, yl, wph, wpl,
                                                          b_proj, out, C_);
}

// round 5
// speedup vs baseline: 3.1537x; 1.0147x over previous
#include <cuda_runtime.h>
#include <cuda_bf16.h>
#include <math.h>
#include <stdint.h>

// Problem constants
constexpr int B_  = 2;
constexpr int T_  = 2048;
constexpr int C_  = 1024;
constexpr int H_  = 16;
constexpr int HD_ = 64;
constexpr int BH_ = B_ * H_;
constexpr int M_  = B_ * T_;     // 4096
constexpr int K_  = C_;          // 1024
constexpr int NQ_ = 3 * C_;      // 3072

// ---------------------------------------------------------------------------
// Device-global scratch
// ---------------------------------------------------------------------------
__device__ __nv_bfloat16 g_qh[BH_ * T_ * HD_], g_ql[BH_ * T_ * HD_];
__device__ __nv_bfloat16 g_kh[BH_ * T_ * HD_], g_kl[BH_ * T_ * HD_];
__device__ __nv_bfloat16 g_vh[BH_ * T_ * HD_], g_vl[BH_ * T_ * HD_];
__device__ __nv_bfloat16 g_yh[M_ * C_],        g_yl[M_ * C_];
__device__ __nv_bfloat16 g_xh[M_ * K_],        g_xl[M_ * K_];
__device__ __nv_bfloat16 g_wah[NQ_ * K_],      g_wal[NQ_ * K_];  // W_attn^T [N,K]
__device__ __nv_bfloat16 g_wph[C_ * K_],       g_wpl[C_ * K_];   // W_proj^T [N,K]

// ---------------------------------------------------------------------------
// PTX helpers (baseline ISA features only)
// ---------------------------------------------------------------------------
__device__ __forceinline__ uint32_t su32(const void* p) {
    uint32_t a;
    asm("{ .reg .u64 t; cvta.to.shared.u64 t, %1; cvt.u32.u64 %0, t; }"
        : "=r"(a) : "l"(p));
    return a;
}

__device__ __forceinline__ void ldm_x4(uint32_t* r, uint32_t addr) {
    asm volatile("ldmatrix.sync.aligned.m8n8.x4.shared.b16 {%0,%1,%2,%3}, [%4];"
        : "=r"(r[0]), "=r"(r[1]), "=r"(r[2]), "=r"(r[3]) : "r"(addr));
}

__device__ __forceinline__ void ldm_x4t(uint32_t* r, uint32_t addr) {
    asm volatile("ldmatrix.sync.aligned.m8n8.x4.trans.shared.b16 {%0,%1,%2,%3}, [%4];"
        : "=r"(r[0]), "=r"(r[1]), "=r"(r[2]), "=r"(r[3]) : "r"(addr));
}

__device__ __forceinline__ void mma_bf16(float* d, const uint32_t* a,
                                         const uint32_t* b) {
    asm volatile(
        "mma.sync.aligned.m16n8k16.row.col.f32.bf16.bf16.f32 "
        "{%0,%1,%2,%3}, {%4,%5,%6,%7}, {%8,%9}, {%0,%1,%2,%3};"
        : "+f"(d[0]), "+f"(d[1]), "+f"(d[2]), "+f"(d[3])
        : "r"(a[0]), "r"(a[1]), "r"(a[2]), "r"(a[3]), "r"(b[0]), "r"(b[1]));
}

__device__ __forceinline__ void cp16(uint32_t saddr, const void* g) {
    asm volatile("cp.async.cg.shared.global [%0], [%1], 16;"
                 :: "r"(saddr), "l"(g));
}
#define CP_COMMIT() asm volatile("cp.async.commit_group;" ::: "memory")
template<int N> __device__ __forceinline__ void cp_wait() {
    asm volatile("cp.async.wait_group %0;" :: "n"(N) : "memory");
}

__device__ __forceinline__ void split1(float a, __nv_bfloat16& h, __nv_bfloat16& l) {
    h = __float2bfloat16_rn(a);
    l = __float2bfloat16_rn(a - __bfloat162float(h));
}
__device__ __forceinline__ uint32_t pack2(float a, float b) {
    __nv_bfloat162 t = __floats2bfloat162_rn(a, b);
    return *(uint32_t*)&t;
}

// ---------------------------------------------------------------------------
// Split x -> bf16 hi/lo
// ---------------------------------------------------------------------------
__global__ void __launch_bounds__(256) split_x(const float* __restrict__ src) {
    const int i = blockIdx.x * 256 + threadIdx.x;   // float4 index
    float4 v = ((const float4*)src)[i];
    __nv_bfloat16 h0, h1, h2, h3, l0, l1, l2, l3;
    split1(v.x, h0, l0); split1(v.y, h1, l1);
    split1(v.z, h2, l2); split1(v.w, h3, l3);
    ((__nv_bfloat162*)g_xh)[2 * i]     = __nv_bfloat162(h0, h1);
    ((__nv_bfloat162*)g_xh)[2 * i + 1] = __nv_bfloat162(h2, h3);
    ((__nv_bfloat162*)g_xl)[2 * i]     = __nv_bfloat162(l0, l1);
    ((__nv_bfloat162*)g_xl)[2 * i + 1] = __nv_bfloat162(l2, l3);
}

// Split + transpose weights: W[K,N] fp32 -> Wt[N,K] bf16 hi/lo
template<int DST>
__global__ void __launch_bounds__(256) split_wT(const float* __restrict__ W,
                                                int Kdim, int Ndim) {
    __nv_bfloat16* Th = (DST == 0) ? g_wah : g_wph;
    __nv_bfloat16* Tl = (DST == 0) ? g_wal : g_wpl;
    __shared__ float t[32][33];
    const int n0 = blockIdx.x * 32, k0 = blockIdx.y * 32;
    const int tx = threadIdx.x & 31, ty = threadIdx.x >> 5;
    #pragma unroll
    for (int r = 0; r < 32; r += 8)
        t[ty + r][tx] = W[(size_t)(k0 + ty + r) * Ndim + n0 + tx];
    __syncthreads();
    #pragma unroll
    for (int r = 0; r < 32; r += 8) {
        const int n = n0 + ty + r, k = k0 + tx;
        __nv_bfloat16 h, l;
        split1(t[tx][ty + r], h, l);
        Th[(size_t)n * Kdim + k] = h;
        Tl[(size_t)n * Kdim + k] = l;
    }
}

// ---------------------------------------------------------------------------
// HMMA GEMM, cp.async double-buffered, 2 CTAs/SM. 128x128 CTA, BK=32,
// 8 warps (2x4). 3-term bf16 hi/lo. EPI=1: QKV scatter.  EPI=0: fp32 store.
// ---------------------------------------------------------------------------
constexpr int GST    = 40;                 // smem row stride (bf16), 32+8 pad
constexpr int GTILE  = 128 * GST;          // bf16 per tile
constexpr int GSTAGE = 4 * GTILE;          // Ah,Al,Bh,Bl
constexpr int GSMEM  = 2 * GSTAGE * 2;     // bytes (2 stages) = 81920
constexpr int GNK    = K_ / 32;            // 32 k-chunks

template<int EPI>
__global__ void __launch_bounds__(256, 2) mma_gemm(
    const __nv_bfloat16* __restrict__ Ah, const __nv_bfloat16* __restrict__ Al,
    const __nv_bfloat16* __restrict__ Bh, const __nv_bfloat16* __restrict__ Bl,
    const float* __restrict__ bias, float* __restrict__ Cout, int N)
{
    extern __shared__ __nv_bfloat16 dsm[];

    const int tid = threadIdx.x;
    const int wid = tid >> 5, lane = tid & 31;
    const int wm = wid >> 2, wn = wid & 3;
    const int m0 = blockIdx.y * 128, n0 = blockIdx.x * 128;

    float acc[4][4][4] = {};

    // ---- stage issue: 4 tiles x 128 rows x 4 uint4 = 2048 cp16, 8/thread
    auto issue = [&](int kt, int stg) {
        const int k0 = kt * 32;
        __nv_bfloat16* s = dsm + stg * GSTAGE;
        #pragma unroll
        for (int it = 0; it < 8; it++) {
            const int idx  = it * 256 + tid;
            const int tile = idx >> 9;
            const int rem  = idx & 511;
            const int row  = rem >> 2;
            const int c8   = (rem & 3) * 8;
            const __nv_bfloat16* gp;
            if      (tile == 0) gp = Ah + (size_t)(m0 + row) * K_ + k0 + c8;
            else if (tile == 1) gp = Al + (size_t)(m0 + row) * K_ + k0 + c8;
            else if (tile == 2) gp = Bh + (size_t)(n0 + row) * K_ + k0 + c8;
            else                gp = Bl + (size_t)(n0 + row) * K_ + k0 + c8;
            cp16(su32(&s[tile * GTILE + row * GST + c8]), gp);
        }
    };

    auto compute = [&](int stg) {
        const __nv_bfloat16* sAh = dsm + stg * GSTAGE;
        const __nv_bfloat16* sAl = sAh + GTILE;
        const __nv_bfloat16* sBh = sAl + GTILE;
        const __nv_bfloat16* sBl = sBh + GTILE;
        #pragma unroll
        for (int ks = 0; ks < 2; ks++) {
            uint32_t ah[4][4], al[4][4];
            const int arow = (lane & 15);
            const int acol = ks * 16 + ((lane >> 4) << 3);
            #pragma unroll
            for (int ti = 0; ti < 4; ti++) {
                const int off = (wm * 64 + ti * 16 + arow) * GST + acol;
                ldm_x4(ah[ti], su32(&sAh[off]));
                ldm_x4(al[ti], su32(&sAl[off]));
            }
            uint32_t bh4[2][4], bl4[2][4];
            const int brow = (lane & 7) + ((lane >> 4) << 3);
            const int bcol = ks * 16 + (((lane >> 3) & 1) << 3);
            #pragma unroll
            for (int tp = 0; tp < 2; tp++) {
                const int off = (wn * 32 + tp * 16 + brow) * GST + bcol;
                ldm_x4(bh4[tp], su32(&sBh[off]));
                ldm_x4(bl4[tp], su32(&sBl[off]));
            }
            #pragma unroll
            for (int ti = 0; ti < 4; ti++)
                #pragma unroll
                for (int tj = 0; tj < 4; tj++) {
                    const uint32_t* bhf = &bh4[tj >> 1][(tj & 1) * 2];
                    const uint32_t* blf = &bl4[tj >> 1][(tj & 1) * 2];
                    mma_bf16(acc[ti][tj], ah[ti], bhf);
                    mma_bf16(acc[ti][tj], ah[ti], blf);
                    mma_bf16(acc[ti][tj], al[ti], bhf);
                }
        }
    };

    issue(0, 0);
    CP_COMMIT();
    #pragma unroll 1
    for (int kt = 0; kt < GNK; kt++) {
        if (kt + 1 < GNK) {
            issue(kt + 1, (kt + 1) & 1);
            CP_COMMIT();
            cp_wait<1>();
        } else {
            cp_wait<0>();
        }
        __syncthreads();
        compute(kt & 1);
        __syncthreads();
    }

    // Epilogue
    #pragma unroll
    for (int ti = 0; ti < 4; ti++) {
        #pragma unroll
        for (int tj = 0; tj < 4; tj++) {
            const int n = n0 + wn * 32 + tj * 8 + 2 * (lane & 3);
            const float b0 = bias[n], b1 = bias[n + 1];
            #pragma unroll
            for (int half = 0; half < 2; half++) {
                const int m = m0 + wm * 64 + ti * 16 + (lane >> 2) + half * 8;
                const float v0 = acc[ti][tj][half * 2 + 0] + b0;
                const float v1 = acc[ti][tj][half * 2 + 1] + b1;
                if (EPI == 0) {
                    float2* p = (float2*)&Cout[(size_t)m * N + n];
                    *p = make_float2(v0, v1);
                } else {
                    const int sel = n >> 10;
                    const int rr  = n & 1023;
                    const int h   = rr >> 6;
                    const int d   = rr & 63;
                    const int bb  = m >> 11;
                    const int t   = m & 2047;
                    const size_t o = (((size_t)bb * H_ + h) * T_ + t) * HD_ + d;
                    __nv_bfloat16 h0, l0, h1, l1;
                    split1(v0, h0, l0); split1(v1, h1, l1);
                    __nv_bfloat16* dh = (sel == 0) ? g_qh : (sel == 1) ? g_kh : g_vh;
                    __nv_bfloat16* dl = (sel == 0) ? g_ql : (sel == 1) ? g_kl : g_vl;
                    *(__nv_bfloat162*)(dh + o) = __nv_bfloat162(h0, h1);
                    *(__nv_bfloat162*)(dl + o) = __nv_bfloat162(l0, l1);
                }
            }
        }
    }
}

// ---------------------------------------------------------------------------
// Causal flash attention on HMMA, cp.async double-buffered K/V tiles.
// CTA = 64 queries, 4 warps x 16 rows; 64-key tiles; 3-term hi/lo mmas.
// ---------------------------------------------------------------------------
constexpr int AST    = 72;               // row stride (bf16)
constexpr int ATILE  = 64 * AST;         // bf16 per tile
constexpr int ASTAGE = 4 * ATILE;        // Kh,Kl,Vh,Vl
constexpr int ASMEM  = 2 * ASTAGE * 2;   // bytes = 73728

__global__ void __launch_bounds__(128) attn_kernel() {
    extern __shared__ __nv_bfloat16 adsm[];

    const int bh  = blockIdx.y;
    const int q0  = blockIdx.x * 64;
    const int tid = threadIdx.x, wid = tid >> 5, lane = tid & 31;
    const int NT  = q0 / 64 + 1;

    const size_t base = (size_t)bh * T_ * HD_;
    const __nv_bfloat16* __restrict__ qhp = g_qh + base;
    const __nv_bfloat16* __restrict__ qlp = g_ql + base;
    const __nv_bfloat16* __restrict__ khp = g_kh + base;
    const __nv_bfloat16* __restrict__ klp = g_kl + base;
    const __nv_bfloat16* __restrict__ vhp = g_vh + base;
    const __nv_bfloat16* __restrict__ vlp = g_vl + base;

    // Stage Q into stage-0 Kh/Kl area, pull A-fragments, then release.
    {
        __nv_bfloat16* sQh = adsm;
        __nv_bfloat16* sQl = adsm + ATILE;
        #pragma unroll
        for (int rr = 0; rr < 4; rr++) {
            const int idx = rr * 128 + tid;          // 512 uint4 slots
            const int row = idx >> 3, c8 = (idx & 7) * 8;
            const size_t g = (size_t)(q0 + row) * HD_ + c8;
            *(uint4*)&sQh[row * AST + c8] = *(const uint4*)(qhp + g);
            *(uint4*)&sQl[row * AST + c8] = *(const uint4*)(qlp + g);
        }
    }
    __syncthreads();

    uint32_t qh[4][4], ql[4][4];
    {
        const int arow = lane & 15;
        const int ac   = (lane >> 4) << 3;
        #pragma unroll
        for (int dt = 0; dt < 4; dt++) {
            const int off = (wid * 16 + arow) * AST + dt * 16 + ac;
            ldm_x4(qh[dt], su32(&adsm[off]));
            ldm_x4(ql[dt], su32(&adsm[ATILE + off]));
        }
    }
    __syncthreads();

    auto issue_kv = [&](int t, int stg) {
        const int k0 = t * 64;
        __nv_bfloat16* s = adsm + stg * ASTAGE;
        #pragma unroll
        for (int it = 0; it < 16; it++) {
            const int idx  = it * 128 + tid;         // 2048 uint4 slots
            const int tile = idx >> 9;
            const int rem  = idx & 511;
            const int row  = rem >> 3;
            const int c8   = (rem & 7) * 8;
            const size_t g = (size_t)(k0 + row) * HD_ + c8;
            const __nv_bfloat16* gp;
            if      (tile == 0) gp = khp + g;
            else if (tile == 1) gp = klp + g;
            else if (tile == 2) gp = vhp + g;
            else                gp = vlp + g;
            cp16(su32(&s[tile * ATILE + row * AST + c8]), gp);
        }
    };

    float of[8][4] = {};
    float m0r = -1e30f, m1r = -1e30f, l0r = 0.f, l1r = 0.f;
    const float scale = 0.03125f;   // 1/sqrt(1024)

    issue_kv(0, 0);
    CP_COMMIT();

    #pragma unroll 1
    for (int t = 0; t < NT; t++) {
        if (t + 1 < NT) {
            issue_kv(t + 1, (t + 1) & 1);
            CP_COMMIT();
            cp_wait<1>();
        } else {
            cp_wait<0>();
        }
        __syncthreads();

        const __nv_bfloat16* sKh = adsm + (t & 1) * ASTAGE;
        const __nv_bfloat16* sKl = sKh + ATILE;
        const __nv_bfloat16* sVh = sKl + ATILE;
        const __nv_bfloat16* sVl = sVh + ATILE;
        const int k0 = t * 64;

        // S = Q K^T (3-term)
        float sf[8][4];
        const int krow = lane & 7;
        const int kc   = (lane >> 3) << 3;
        #pragma unroll
        for (int nt = 0; nt < 8; nt++) {
            sf[nt][0] = sf[nt][1] = sf[nt][2] = sf[nt][3] = 0.f;
            uint32_t kh0[4], kh1[4], kl0[4], kl1[4];
            const int off0 = (nt * 8 + krow) * AST + kc;
            const int off1 = off0 + 32;
            ldm_x4(kh0, su32(&sKh[off0]));
            ldm_x4(kh1, su32(&sKh[off1]));
            ldm_x4(kl0, su32(&sKl[off0]));
            ldm_x4(kl1, su32(&sKl[off1]));
            #pragma unroll
            for (int dt = 0; dt < 4; dt++) {
                const uint32_t* khf = (dt < 2) ? &kh0[(dt & 1) * 2] : &kh1[(dt & 1) * 2];
                const uint32_t* klf = (dt < 2) ? &kl0[(dt & 1) * 2] : &kl1[(dt & 1) * 2];
                mma_bf16(sf[nt], qh[dt], khf);
                mma_bf16(sf[nt], qh[dt], klf);
                mma_bf16(sf[nt], ql[dt], khf);
            }
        }

        // scale + causal mask (diagonal tile only)
        const int rr0 = wid * 16 + (lane >> 2);
        #pragma unroll
        for (int nt = 0; nt < 8; nt++) {
            #pragma unroll
            for (int e = 0; e < 4; e++) sf[nt][e] *= scale;
        }
        if (k0 == q0) {
            #pragma unroll
            for (int nt = 0; nt < 8; nt++) {
                const int col = nt * 8 + 2 * (lane & 3);
                #pragma unroll
                for (int e = 0; e < 4; e++) {
                    const int c = col + (e & 1);
                    const int r = rr0 + ((e >> 1) << 3);
                    if (c > r) sf[nt][e] = -1e30f;
                }
            }
        }

        // Online softmax stats
        float mt0 = -1e30f, mt1 = -1e30f;
        #pragma unroll
        for (int nt = 0; nt < 8; nt++) {
            mt0 = fmaxf(mt0, fmaxf(sf[nt][0], sf[nt][1]));
            mt1 = fmaxf(mt1, fmaxf(sf[nt][2], sf[nt][3]));
        }
        mt0 = fmaxf(mt0, __shfl_xor_sync(0xffffffff, mt0, 1));
        mt0 = fmaxf(mt0, __shfl_xor_sync(0xffffffff, mt0, 2));
        mt1 = fmaxf(mt1, __shfl_xor_sync(0xffffffff, mt1, 1));
        mt1 = fmaxf(mt1, __shfl_xor_sync(0xffffffff, mt1, 2));

        const float mn0 = fmaxf(m0r, mt0), mn1 = fmaxf(m1r, mt1);
        const float c0 = __expf(m0r - mn0), c1 = __expf(m1r - mn1);

        float ls0 = 0.f, ls1 = 0.f;
        #pragma unroll
        for (int nt = 0; nt < 8; nt++) {
            sf[nt][0] = __expf(sf[nt][0] - mn0);
            sf[nt][1] = __expf(sf[nt][1] - mn0);
            sf[nt][2] = __expf(sf[nt][2] - mn1);
            sf[nt][3] = __expf(sf[nt][3] - mn1);
            ls0 += sf[nt][0] + sf[nt][1];
            ls1 += sf[nt][2] + sf[nt][3];
        }
        ls0 += __shfl_xor_sync(0xffffffff, ls0, 1);
        ls0 += __shfl_xor_sync(0xffffffff, ls0, 2);
        ls1 += __shfl_xor_sync(0xffffffff, ls1, 1);
        ls1 += __shfl_xor_sync(0xffffffff, ls1, 2);

        l0r = l0r * c0 + ls0;
        l1r = l1r * c1 + ls1;
        m0r = mn0; m1r = mn1;

        #pragma unroll
        for (int nt = 0; nt < 8; nt++) {
            of[nt][0] *= c0; of[nt][1] *= c0;
            of[nt][2] *= c1; of[nt][3] *= c1;
        }

        // Pack P into A-fragments (hi/lo)
        uint32_t ph[4][4], pl[4][4];
        #pragma unroll
        for (int kt = 0; kt < 4; kt++) {
            #pragma unroll
            for (int q = 0; q < 4; q++) {
                const float a = sf[2 * kt + (q >> 1)][(q & 1) * 2 + 0];
                const float b = sf[2 * kt + (q >> 1)][(q & 1) * 2 + 1];
                __nv_bfloat16 ha, la, hb, lb;
                split1(a, ha, la); split1(b, hb, lb);
                ph[kt][q] = pack2(__bfloat162float(ha), __bfloat162float(hb));
                pl[kt][q] = pack2(__bfloat162float(la), __bfloat162float(lb));
            }
        }

        // O += P V (3-term)
        #pragma unroll
        for (int ntd = 0; ntd < 8; ntd++) {
            uint32_t vha[4], vhb[4], vla[4], vlb[4];
            const int offa = (lane)      * AST + ntd * 8;
            const int offb = (32 + lane) * AST + ntd * 8;
            ldm_x4t(vha, su32(&sVh[offa]));
            ldm_x4t(vhb, su32(&sVh[offb]));
            ldm_x4t(vla, su32(&sVl[offa]));
            ldm_x4t(vlb, su32(&sVl[offb]));
            #pragma unroll
            for (int kt = 0; kt < 4; kt++) {
                const uint32_t* vhf = (kt < 2) ? &vha[(kt & 1) * 2] : &vhb[(kt & 1) * 2];
                const uint32_t* vlf = (kt < 2) ? &vla[(kt & 1) * 2] : &vlb[(kt & 1) * 2];
                mma_bf16(of[ntd], ph[kt], vhf);
                mma_bf16(of[ntd], ph[kt], vlf);
                mma_bf16(of[ntd], pl[kt], vhf);
            }
        }
        __syncthreads();
    }

    // Normalize + store y as bf16 hi/lo (proj GEMM A operand)
    const float inv0 = 1.f / l0r, inv1 = 1.f / l1r;
    const int b = bh >> 4, h = bh & 15;
    const int row0 = q0 + wid * 16 + (lane >> 2);
    const int dx = 2 * (lane & 3);
    #pragma unroll
    for (int ntd = 0; ntd < 8; ntd++) {
        const int d = h * HD_ + ntd * 8 + dx;
        {
            const float y0 = of[ntd][0] * inv0, y1 = of[ntd][1] * inv0;
            __nv_bfloat16 h0, l0, h1, l1;
            split1(y0, h0, l0); split1(y1, h1, l1);
            const size_t o = ((size_t)b * T_ + row0) * C_ + d;
            *(__nv_bfloat162*)(g_yh + o) = __nv_bfloat162(h0, h1);
            *(__nv_bfloat162*)(g_yl + o) = __nv_bfloat162(l0, l1);
        }
        {
            const float y0 = of[ntd][2] * inv1, y1 = of[ntd][3] * inv1;
            __nv_bfloat16 h0, l0, h1, l1;
            split1(y0, h0, l0); split1(y1, h1, l1);
            const size_t o = ((size_t)b * T_ + row0 + 8) * C_ + d;
            *(__nv_bfloat162*)(g_yh + o) = __nv_bfloat162(h0, h1);
            *(__nv_bfloat162*)(g_yl + o) = __nv_bfloat162(l0, l1);
        }
    }
}

// ---------------------------------------------------------------------------
// Launch
// ---------------------------------------------------------------------------
extern "C" void kernel_launch(void* const* d_in, const int* in_sizes, int n_in,
                              void* d_out, int out_size)
{
    const float* x      = (const float*)d_in[0];
    const float* W_attn = (const float*)d_in[1];
    const float* b_attn = (const float*)d_in[2];
    const float* W_proj = (const float*)d_in[3];
    const float* b_proj = (const float*)d_in[4];
    float* out = (float*)d_out;

    __nv_bfloat16 *xh, *xl, *wah, *wal, *wph, *wpl, *yh, *yl;
    cudaGetSymbolAddress((void**)&xh,  g_xh);
    cudaGetSymbolAddress((void**)&xl,  g_xl);
    cudaGetSymbolAddress((void**)&wah, g_wah);
    cudaGetSymbolAddress((void**)&wal, g_wal);
    cudaGetSymbolAddress((void**)&wph, g_wph);
    cudaGetSymbolAddress((void**)&wpl, g_wpl);
    cudaGetSymbolAddress((void**)&yh,  g_yh);
    cudaGetSymbolAddress((void**)&yl,  g_yl);

    cudaFuncSetAttribute(mma_gemm<1>, cudaFuncAttributeMaxDynamicSharedMemorySize, GSMEM);
    cudaFuncSetAttribute(mma_gemm<0>, cudaFuncAttributeMaxDynamicSharedMemorySize, GSMEM);
    cudaFuncSetAttribute(attn_kernel, cudaFuncAttributeMaxDynamicSharedMemorySize, ASMEM);

    // 1) splits
    split_x<<<(M_ * K_) / 1024, 256>>>(x);
    split_wT<0><<<dim3(NQ_ / 32, K_ / 32), 256>>>(W_attn, K_, NQ_);
    split_wT<1><<<dim3(C_ / 32, K_ / 32), 256>>>(W_proj, K_, C_);

    // 2) QKV GEMM -> q/k/v hi/lo
    mma_gemm<1><<<dim3(NQ_ / 128, M_ / 128), 256, GSMEM>>>(xh, xl, wah, wal,
                                                           b_attn, nullptr, NQ_);
    // 3) causal attention -> y hi/lo
    attn_kernel<<<dim3(T_ / 64, BH_), 128, ASMEM>>>();

    // 4) proj GEMM -> out
    mma_gemm<0><<<dim3(C_ / 128, M_ / 128), 256, GSMEM>>>(yh, yl, wph, wpl,
                                                          b_proj, out, C_);
}

// round 7
// speedup vs baseline: 3.3575x; 1.0646x over previous
#include <cuda_runtime.h>
#include <cuda_bf16.h>
#include <math.h>
#include <stdint.h>

// Problem constants
constexpr int B_  = 2;
constexpr int T_  = 2048;
constexpr int C_  = 1024;
constexpr int H_  = 16;
constexpr int HD_ = 64;
constexpr int BH_ = B_ * H_;
constexpr int M_  = B_ * T_;     // 4096
constexpr int K_  = C_;          // 1024
constexpr int NQ_ = 3 * C_;      // 3072

// ---------------------------------------------------------------------------
// Device-global scratch
// ---------------------------------------------------------------------------
__device__ __nv_bfloat16 g_qh[BH_ * T_ * HD_], g_ql[BH_ * T_ * HD_];
__device__ __nv_bfloat16 g_kh[BH_ * T_ * HD_], g_kl[BH_ * T_ * HD_];
__device__ __nv_bfloat16 g_vh[BH_ * T_ * HD_], g_vl[BH_ * T_ * HD_];
__device__ __nv_bfloat16 g_yh[M_ * C_],        g_yl[M_ * C_];
__device__ __nv_bfloat16 g_xh[M_ * K_],        g_xl[M_ * K_];
__device__ __nv_bfloat16 g_wah[NQ_ * K_],      g_wal[NQ_ * K_];  // W_attn^T [N,K]
__device__ __nv_bfloat16 g_wph[C_ * K_],       g_wpl[C_ * K_];   // W_proj^T [N,K]

// ---------------------------------------------------------------------------
// PTX helpers (baseline ISA features only)
// ---------------------------------------------------------------------------
__device__ __forceinline__ uint32_t su32(const void* p) {
    uint32_t a;
    asm("{ .reg .u64 t; cvta.to.shared.u64 t, %1; cvt.u32.u64 %0, t; }"
        : "=r"(a) : "l"(p));
    return a;
}

__device__ __forceinline__ void ldm_x4(uint32_t* r, uint32_t addr) {
    asm volatile("ldmatrix.sync.aligned.m8n8.x4.shared.b16 {%0,%1,%2,%3}, [%4];"
        : "=r"(r[0]), "=r"(r[1]), "=r"(r[2]), "=r"(r[3]) : "r"(addr));
}

__device__ __forceinline__ void ldm_x4t(uint32_t* r, uint32_t addr) {
    asm volatile("ldmatrix.sync.aligned.m8n8.x4.trans.shared.b16 {%0,%1,%2,%3}, [%4];"
        : "=r"(r[0]), "=r"(r[1]), "=r"(r[2]), "=r"(r[3]) : "r"(addr));
}

__device__ __forceinline__ void mma_bf16(float* d, const uint32_t* a,
                                         const uint32_t* b) {
    asm volatile(
        "mma.sync.aligned.m16n8k16.row.col.f32.bf16.bf16.f32 "
        "{%0,%1,%2,%3}, {%4,%5,%6,%7}, {%8,%9}, {%0,%1,%2,%3};"
        : "+f"(d[0]), "+f"(d[1]), "+f"(d[2]), "+f"(d[3])
        : "r"(a[0]), "r"(a[1]), "r"(a[2]), "r"(a[3]), "r"(b[0]), "r"(b[1]));
}

__device__ __forceinline__ void cp16(uint32_t saddr, const void* g) {
    asm volatile("cp.async.cg.shared.global [%0], [%1], 16;"
                 :: "r"(saddr), "l"(g));
}
#define CP_COMMIT() asm volatile("cp.async.commit_group;" ::: "memory")
template<int N> __device__ __forceinline__ void cp_wait() {
    asm volatile("cp.async.wait_group %0;" :: "n"(N) : "memory");
}

__device__ __forceinline__ void split1(float a, __nv_bfloat16& h, __nv_bfloat16& l) {
    h = __float2bfloat16_rn(a);
    l = __float2bfloat16_rn(a - __bfloat162float(h));
}
__device__ __forceinline__ uint32_t pack2(float a, float b) {
    __nv_bfloat162 t = __floats2bfloat162_rn(a, b);
    return *(uint32_t*)&t;
}

// ---------------------------------------------------------------------------
// Split x -> bf16 hi/lo
// ---------------------------------------------------------------------------
__global__ void __launch_bounds__(256) split_x(const float* __restrict__ src) {
    const int i = blockIdx.x * 256 + threadIdx.x;   // float4 index
    float4 v = ((const float4*)src)[i];
    __nv_bfloat16 h0, h1, h2, h3, l0, l1, l2, l3;
    split1(v.x, h0, l0); split1(v.y, h1, l1);
    split1(v.z, h2, l2); split1(v.w, h3, l3);
    ((__nv_bfloat162*)g_xh)[2 * i]     = __nv_bfloat162(h0, h1);
    ((__nv_bfloat162*)g_xh)[2 * i + 1] = __nv_bfloat162(h2, h3);
    ((__nv_bfloat162*)g_xl)[2 * i]     = __nv_bfloat162(l0, l1);
    ((__nv_bfloat162*)g_xl)[2 * i + 1] = __nv_bfloat162(l2, l3);
}

// Split + transpose weights: W[K,N] fp32 -> Wt[N,K] bf16 hi/lo
template<int DST>
__global__ void __launch_bounds__(256) split_wT(const float* __restrict__ W,
                                                int Kdim, int Ndim) {
    __nv_bfloat16* Th = (DST == 0) ? g_wah : g_wph;
    __nv_bfloat16* Tl = (DST == 0) ? g_wal : g_wpl;
    __shared__ float t[32][33];
    const int n0 = blockIdx.x * 32, k0 = blockIdx.y * 32;
    const int tx = threadIdx.x & 31, ty = threadIdx.x >> 5;
    #pragma unroll
    for (int r = 0; r < 32; r += 8)
        t[ty + r][tx] = W[(size_t)(k0 + ty + r) * Ndim + n0 + tx];
    __syncthreads();
    #pragma unroll
    for (int r = 0; r < 32; r += 8) {
        const int n = n0 + ty + r, k = k0 + tx;
        __nv_bfloat16 h, l;
        split1(t[tx][ty + r], h, l);
        Th[(size_t)n * Kdim + k] = h;
        Tl[(size_t)n * Kdim + k] = l;
    }
}

// ---------------------------------------------------------------------------
// HMMA GEMM: 3-stage cp.async pipeline, ONE barrier per chunk, 2 CTAs/SM.
// 128x128 CTA, BK=32, 8 warps (2x4). 3-term bf16 hi/lo.
// Smem: GST=32 (no pad, 16B-aligned rows) + XOR chunk swizzle for
// conflict-free ldmatrix: chunk' = chunk ^ ((row>>1)&3).
// EPI=1: QKV scatter.  EPI=0: fp32 store.
// ---------------------------------------------------------------------------
constexpr int GST    = 32;                 // smem row stride (bf16), no pad
constexpr int GTILE  = 128 * GST;          // bf16 per tile
constexpr int GSTAGE = 4 * GTILE;          // Ah,Al,Bh,Bl
constexpr int GSMEM  = 3 * GSTAGE * 2;     // bytes (3 stages) = 98304
constexpr int GNK    = K_ / 32;            // 32 k-chunks

// element offset of (row, col) under the chunk swizzle; col is a multiple of 8
__device__ __forceinline__ int gswz(int row, int col) {
    return row * GST + ((((col >> 3) ^ ((row >> 1) & 3)) << 3));
}

template<int EPI>
__global__ void __launch_bounds__(256, 2) mma_gemm(
    const __nv_bfloat16* __restrict__ Ah, const __nv_bfloat16* __restrict__ Al,
    const __nv_bfloat16* __restrict__ Bh, const __nv_bfloat16* __restrict__ Bl,
    const float* __restrict__ bias, float* __restrict__ Cout, int N)
{
    extern __shared__ __nv_bfloat16 dsm[];

    const int tid = threadIdx.x;
    const int wid = tid >> 5, lane = tid & 31;
    const int wm = wid >> 2, wn = wid & 3;
    const int m0 = blockIdx.y * 128, n0 = blockIdx.x * 128;

    float acc[4][4][4] = {};

    // ---- stage issue: 4 tiles x 128 rows x 4 uint4 = 2048 cp16, 8/thread
    auto issue = [&](int kt, int stg) {
        const int k0 = kt * 32;
        __nv_bfloat16* s = dsm + stg * GSTAGE;
        #pragma unroll
        for (int it = 0; it < 8; it++) {
            const int idx  = it * 256 + tid;
            const int tile = idx >> 9;
            const int rem  = idx & 511;
            const int row  = rem >> 2;
            const int c8   = (rem & 3) * 8;
            const __nv_bfloat16* gp;
            if      (tile == 0) gp = Ah + (size_t)(m0 + row) * K_ + k0 + c8;
            else if (tile == 1) gp = Al + (size_t)(m0 + row) * K_ + k0 + c8;
            else if (tile == 2) gp = Bh + (size_t)(n0 + row) * K_ + k0 + c8;
            else                gp = Bl + (size_t)(n0 + row) * K_ + k0 + c8;
            cp16(su32(&s[tile * GTILE + gswz(row, c8)]), gp);
        }
    };

    auto compute = [&](int stg) {
        const __nv_bfloat16* sAh = dsm + stg * GSTAGE;
        const __nv_bfloat16* sAl = sAh + GTILE;
        const __nv_bfloat16* sBh = sAl + GTILE;
        const __nv_bfloat16* sBl = sBh + GTILE;
        #pragma unroll
        for (int ks = 0; ks < 2; ks++) {
            uint32_t ah[4][4], al[4][4];
            const int arow = (lane & 15);
            const int acol = ks * 16 + ((lane >> 4) << 3);
            #pragma unroll
            for (int ti = 0; ti < 4; ti++) {
                const int off = gswz(wm * 64 + ti * 16 + arow, acol);
                ldm_x4(ah[ti], su32(&sAh[off]));
                ldm_x4(al[ti], su32(&sAl[off]));
            }
            uint32_t bh4[2][4], bl4[2][4];
            const int brow = (lane & 7) + ((lane >> 4) << 3);
            const int bcol = ks * 16 + (((lane >> 3) & 1) << 3);
            #pragma unroll
            for (int tp = 0; tp < 2; tp++) {
                const int off = gswz(wn * 32 + tp * 16 + brow, bcol);
                ldm_x4(bh4[tp], su32(&sBh[off]));
                ldm_x4(bl4[tp], su32(&sBl[off]));
            }
            #pragma unroll
            for (int ti = 0; ti < 4; ti++)
                #pragma unroll
                for (int tj = 0; tj < 4; tj++) {
                    const uint32_t* bhf = &bh4[tj >> 1][(tj & 1) * 2];
                    const uint32_t* blf = &bl4[tj >> 1][(tj & 1) * 2];
                    mma_bf16(acc[ti][tj], ah[ti], bhf);
                    mma_bf16(acc[ti][tj], ah[ti], blf);
                    mma_bf16(acc[ti][tj], al[ti], bhf);
                }
        }
    };

    // 3-stage pipeline, depth-2 prefetch, single barrier per chunk.
    // issue(kt+2) writes stage (kt-1)%3, whose readers (compute(kt-1))
    // all passed this iteration's __syncthreads.
    issue(0, 0);
    CP_COMMIT();
    issue(1, 1);
    CP_COMMIT();
    #pragma unroll 1
    for (int kt = 0; kt < GNK; kt++) {
        if (kt + 1 < GNK) cp_wait<1>(); else cp_wait<0>();
        __syncthreads();
        compute(kt % 3);
        if (kt + 2 < GNK) {
            issue(kt + 2, (kt + 2) % 3);
            CP_COMMIT();
        }
    }

    // Epilogue
    #pragma unroll
    for (int ti = 0; ti < 4; ti++) {
        #pragma unroll
        for (int tj = 0; tj < 4; tj++) {
            const int n = n0 + wn * 32 + tj * 8 + 2 * (lane & 3);
            const float b0 = bias[n], b1 = bias[n + 1];
            #pragma unroll
            for (int half = 0; half < 2; half++) {
                const int m = m0 + wm * 64 + ti * 16 + (lane >> 2) + half * 8;
                const float v0 = acc[ti][tj][half * 2 + 0] + b0;
                const float v1 = acc[ti][tj][half * 2 + 1] + b1;
                if (EPI == 0) {
                    float2* p = (float2*)&Cout[(size_t)m * N + n];
                    *p = make_float2(v0, v1);
                } else {
                    const int sel = n >> 10;
                    const int rr  = n & 1023;
                    const int h   = rr >> 6;
                    const int d   = rr & 63;
                    const int bb  = m >> 11;
                    const int t   = m & 2047;
                    const size_t o = (((size_t)bb * H_ + h) * T_ + t) * HD_ + d;
                    __nv_bfloat16 h0, l0, h1, l1;
                    split1(v0, h0, l0); split1(v1, h1, l1);
                    __nv_bfloat16* dh = (sel == 0) ? g_qh : (sel == 1) ? g_kh : g_vh;
                    __nv_bfloat16* dl = (sel == 0) ? g_ql : (sel == 1) ? g_kl : g_vl;
                    *(__nv_bfloat162*)(dh + o) = __nv_bfloat162(h0, h1);
                    *(__nv_bfloat162*)(dl + o) = __nv_bfloat162(l0, l1);
                }
            }
        }
    }
}

// ---------------------------------------------------------------------------
// Causal flash attention on HMMA, cp.async double-buffered K/V tiles.
// CTA = 64 queries, 4 warps x 16 rows; 64-key tiles; 3-term hi/lo mmas.
// Longest-first scheduling: blockIdx.x reversed so diagonal-heavy CTAs
// launch in the first wave. AST=72 bf16 = 144 bytes (16B aligned).
// ---------------------------------------------------------------------------
constexpr int AST    = 72;               // row stride (bf16)
constexpr int ATILE  = 64 * AST;         // bf16 per tile
constexpr int ASTAGE = 4 * ATILE;        // Kh,Kl,Vh,Vl
constexpr int ASMEM  = 2 * ASTAGE * 2;   // bytes = 73728

__global__ void __launch_bounds__(128) attn_kernel() {
    extern __shared__ __nv_bfloat16 adsm[];

    const int bh  = blockIdx.y;
    const int q0  = (gridDim.x - 1 - blockIdx.x) * 64;   // longest-first
    const int tid = threadIdx.x, wid = tid >> 5, lane = tid & 31;
    const int NT  = q0 / 64 + 1;

    const size_t base = (size_t)bh * T_ * HD_;
    const __nv_bfloat16* __restrict__ qhp = g_qh + base;
    const __nv_bfloat16* __restrict__ qlp = g_ql + base;
    const __nv_bfloat16* __restrict__ khp = g_kh + base;
    const __nv_bfloat16* __restrict__ klp = g_kl + base;
    const __nv_bfloat16* __restrict__ vhp = g_vh + base;
    const __nv_bfloat16* __restrict__ vlp = g_vl + base;

    // Stage Q into stage-0 Kh/Kl area, pull A-fragments, then release.
    {
        __nv_bfloat16* sQh = adsm;
        __nv_bfloat16* sQl = adsm + ATILE;
        #pragma unroll
        for (int rr = 0; rr < 4; rr++) {
            const int idx = rr * 128 + tid;          // 512 uint4 slots
            const int row = idx >> 3, c8 = (idx & 7) * 8;
            const size_t g = (size_t)(q0 + row) * HD_ + c8;
            *(uint4*)&sQh[row * AST + c8] = *(const uint4*)(qhp + g);
            *(uint4*)&sQl[row * AST + c8] = *(const uint4*)(qlp + g);
        }
    }
    __syncthreads();

    uint32_t qh[4][4], ql[4][4];
    {
        const int arow = lane & 15;
        const int ac   = (lane >> 4) << 3;
        #pragma unroll
        for (int dt = 0; dt < 4; dt++) {
            const int off = (wid * 16 + arow) * AST + dt * 16 + ac;
            ldm_x4(qh[dt], su32(&adsm[off]));
            ldm_x4(ql[dt], su32(&adsm[ATILE + off]));
        }
    }
    __syncthreads();

    auto issue_kv = [&](int t, int stg) {
        const int k0 = t * 64;
        __nv_bfloat16* s = adsm + stg * ASTAGE;
        #pragma unroll
        for (int it = 0; it < 16; it++) {
            const int idx  = it * 128 + tid;         // 2048 uint4 slots
            const int tile = idx >> 9;
            const int rem  = idx & 511;
            const int row  = rem >> 3;
            const int c8   = (rem & 7) * 8;
            const size_t g = (size_t)(k0 + row) * HD_ + c8;
            const __nv_bfloat16* gp;
            if      (tile == 0) gp = khp + g;
            else if (tile == 1) gp = klp + g;
            else if (tile == 2) gp = vhp + g;
            else                gp = vlp + g;
            cp16(su32(&s[tile * ATILE + row * AST + c8]), gp);
        }
    };

    float of[8][4] = {};
    float m0r = -1e30f, m1r = -1e30f, l0r = 0.f, l1r = 0.f;
    const float scale = 0.03125f;   // 1/sqrt(1024)

    issue_kv(0, 0);
    CP_COMMIT();

    #pragma unroll 1
    for (int t = 0; t < NT; t++) {
        if (t + 1 < NT) {
            issue_kv(t + 1, (t + 1) & 1);
            CP_COMMIT();
            cp_wait<1>();
        } else {
            cp_wait<0>();
        }
        __syncthreads();

        const __nv_bfloat16* sKh = adsm + (t & 1) * ASTAGE;
        const __nv_bfloat16* sKl = sKh + ATILE;
        const __nv_bfloat16* sVh = sKl + ATILE;
        const __nv_bfloat16* sVl = sVh + ATILE;
        const int k0 = t * 64;

        // S = Q K^T (3-term)
        float sf[8][4];
        const int krow = lane & 7;
        const int kc   = (lane >> 3) << 3;
        #pragma unroll
        for (int nt = 0; nt < 8; nt++) {
            sf[nt][0] = sf[nt][1] = sf[nt][2] = sf[nt][3] = 0.f;
            uint32_t kh0[4], kh1[4], kl0[4], kl1[4];
            const int off0 = (nt * 8 + krow) * AST + kc;
            const int off1 = off0 + 32;
            ldm_x4(kh0, su32(&sKh[off0]));
            ldm_x4(kh1, su32(&sKh[off1]));
            ldm_x4(kl0, su32(&sKl[off0]));
            ldm_x4(kl1, su32(&sKl[off1]));
            #pragma unroll
            for (int dt = 0; dt < 4; dt++) {
                const uint32_t* khf = (dt < 2) ? &kh0[(dt & 1) * 2] : &kh1[(dt & 1) * 2];
                const uint32_t* klf = (dt < 2) ? &kl0[(dt & 1) * 2] : &kl1[(dt & 1) * 2];
                mma_bf16(sf[nt], qh[dt], khf);
                mma_bf16(sf[nt], qh[dt], klf);
                mma_bf16(sf[nt], ql[dt], khf);
            }
        }

        // scale + causal mask (diagonal tile only)
        const int rr0 = wid * 16 + (lane >> 2);
        #pragma unroll
        for (int nt = 0; nt < 8; nt++) {
            #pragma unroll
            for (int e = 0; e < 4; e++) sf[nt][e] *= scale;
        }
        if (k0 == q0) {
            #pragma unroll
            for (int nt = 0; nt < 8; nt++) {
                const int col = nt * 8 + 2 * (lane & 3);
                #pragma unroll
                for (int e = 0; e < 4; e++) {
                    const int c = col + (e & 1);
                    const int r = rr0 + ((e >> 1) << 3);
                    if (c > r) sf[nt][e] = -1e30f;
                }
            }
        }

        // Online softmax stats
        float mt0 = -1e30f, mt1 = -1e30f;
        #pragma unroll
        for (int nt = 0; nt < 8; nt++) {
            mt0 = fmaxf(mt0, fmaxf(sf[nt][0], sf[nt][1]));
            mt1 = fmaxf(mt1, fmaxf(sf[nt][2], sf[nt][3]));
        }
        mt0 = fmaxf(mt0, __shfl_xor_sync(0xffffffff, mt0, 1));
        mt0 = fmaxf(mt0, __shfl_xor_sync(0xffffffff, mt0, 2));
        mt1 = fmaxf(mt1, __shfl_xor_sync(0xffffffff, mt1, 1));
        mt1 = fmaxf(mt1, __shfl_xor_sync(0xffffffff, mt1, 2));

        const float mn0 = fmaxf(m0r, mt0), mn1 = fmaxf(m1r, mt1);
        const float c0 = __expf(m0r - mn0), c1 = __expf(m1r - mn1);

        float ls0 = 0.f, ls1 = 0.f;
        #pragma unroll
        for (int nt = 0; nt < 8; nt++) {
            sf[nt][0] = __expf(sf[nt][0] - mn0);
            sf[nt][1] = __expf(sf[nt][1] - mn0);
            sf[nt][2] = __expf(sf[nt][2] - mn1);
            sf[nt][3] = __expf(sf[nt][3] - mn1);
            ls0 += sf[nt][0] + sf[nt][1];
            ls1 += sf[nt][2] + sf[nt][3];
        }
        ls0 += __shfl_xor_sync(0xffffffff, ls0, 1);
        ls0 += __shfl_xor_sync(0xffffffff, ls0, 2);
        ls1 += __shfl_xor_sync(0xffffffff, ls1, 1);
        ls1 += __shfl_xor_sync(0xffffffff, ls1, 2);

        l0r = l0r * c0 + ls0;
        l1r = l1r * c1 + ls1;
        m0r = mn0; m1r = mn1;

        #pragma unroll
        for (int nt = 0; nt < 8; nt++) {
            of[nt][0] *= c0; of[nt][1] *= c0;
            of[nt][2] *= c1; of[nt][3] *= c1;
        }

        // Pack P into A-fragments (hi/lo)
        uint32_t ph[4][4], pl[4][4];
        #pragma unroll
        for (int kt = 0; kt < 4; kt++) {
            #pragma unroll
            for (int q = 0; q < 4; q++) {
                const float a = sf[2 * kt + (q >> 1)][(q & 1) * 2 + 0];
                const float b = sf[2 * kt + (q >> 1)][(q & 1) * 2 + 1];
                __nv_bfloat16 ha, la, hb, lb;
                split1(a, ha, la); split1(b, hb, lb);
                ph[kt][q] = pack2(__bfloat162float(ha), __bfloat162float(hb));
                pl[kt][q] = pack2(__bfloat162float(la), __bfloat162float(lb));
            }
        }

        // O += P V (3-term)
        #pragma unroll
        for (int ntd = 0; ntd < 8; ntd++) {
            uint32_t vha[4], vhb[4], vla[4], vlb[4];
            const int offa = (lane)      * AST + ntd * 8;
            const int offb = (32 + lane) * AST + ntd * 8;
            ldm_x4t(vha, su32(&sVh[offa]));
            ldm_x4t(vhb, su32(&sVh[offb]));
            ldm_x4t(vla, su32(&sVl[offa]));
            ldm_x4t(vlb, su32(&sVl[offb]));
            #pragma unroll
            for (int kt = 0; kt < 4; kt++) {
                const uint32_t* vhf = (kt < 2) ? &vha[(kt & 1) * 2] : &vhb[(kt & 1) * 2];
                const uint32_t* vlf = (kt < 2) ? &vla[(kt & 1) * 2] : &vlb[(kt & 1) * 2];
                mma_bf16(of[ntd], ph[kt], vhf);
                mma_bf16(of[ntd], ph[kt], vlf);
                mma_bf16(of[ntd], pl[kt], vhf);
            }
        }
        __syncthreads();
    }

    // Normalize + store y as bf16 hi/lo (proj GEMM A operand)
    const float inv0 = 1.f / l0r, inv1 = 1.f / l1r;
    const int b = bh >> 4, h = bh & 15;
    const int row0 = q0 + wid * 16 + (lane >> 2);
    const int dx = 2 * (lane & 3);
    #pragma unroll
    for (int ntd = 0; ntd < 8; ntd++) {
        const int d = h * HD_ + ntd * 8 + dx;
        {
            const float y0 = of[ntd][0] * inv0, y1 = of[ntd][1] * inv0;
            __nv_bfloat16 h0, l0, h1, l1;
            split1(y0, h0, l0); split1(y1, h1, l1);
            const size_t o = ((size_t)b * T_ + row0) * C_ + d;
            *(__nv_bfloat162*)(g_yh + o) = __nv_bfloat162(h0, h1);
            *(__nv_bfloat162*)(g_yl + o) = __nv_bfloat162(l0, l1);
        }
        {
            const float y0 = of[ntd][2] * inv1, y1 = of[ntd][3] * inv1;
            __nv_bfloat16 h0, l0, h1, l1;
            split1(y0, h0, l0); split1(y1, h1, l1);
            const size_t o = ((size_t)b * T_ + row0 + 8) * C_ + d;
            *(__nv_bfloat162*)(g_yh + o) = __nv_bfloat162(h0, h1);
            *(__nv_bfloat162*)(g_yl + o) = __nv_bfloat162(l0, l1);
        }
    }
}

// ---------------------------------------------------------------------------
// Launch
// ---------------------------------------------------------------------------
extern "C" void kernel_launch(void* const* d_in, const int* in_sizes, int n_in,
                              void* d_out, int out_size)
{
    const float* x      = (const float*)d_in[0];
    const float* W_attn = (const float*)d_in[1];
    const float* b_attn = (const float*)d_in[2];
    const float* W_proj = (const float*)d_in[3];
    const float* b_proj = (const float*)d_in[4];
    float* out = (float*)d_out;

    __nv_bfloat16 *xh, *xl, *wah, *wal, *wph, *wpl, *yh, *yl;
    cudaGetSymbolAddress((void**)&xh,  g_xh);
    cudaGetSymbolAddress((void**)&xl,  g_xl);
    cudaGetSymbolAddress((void**)&wah, g_wah);
    cudaGetSymbolAddress((void**)&wal, g_wal);
    cudaGetSymbolAddress((void**)&wph, g_wph);
    cudaGetSymbolAddress((void**)&wpl, g_wpl);
    cudaGetSymbolAddress((void**)&yh,  g_yh);
    cudaGetSymbolAddress((void**)&yl,  g_yl);

    cudaFuncSetAttribute(mma_gemm<1>, cudaFuncAttributeMaxDynamicSharedMemorySize, GSMEM);
    cudaFuncSetAttribute(mma_gemm<0>, cudaFuncAttributeMaxDynamicSharedMemorySize, GSMEM);
    cudaFuncSetAttribute(attn_kernel, cudaFuncAttributeMaxDynamicSharedMemorySize, ASMEM);

    // 1) splits
    split_x<<<(M_ * K_) / 1024, 256>>>(x);
    split_wT<0><<<dim3(NQ_ / 32, K_ / 32), 256>>>(W_attn, K_, NQ_);
    split_wT<1><<<dim3(C_ / 32, K_ / 32), 256>>>(W_proj, K_, C_);

    // 2) QKV GEMM -> q/k/v hi/lo
    mma_gemm<1><<<dim3(NQ_ / 128, M_ / 128), 256, GSMEM>>>(xh, xl, wah, wal,
                                                           b_attn, nullptr, NQ_);
    // 3) causal attention -> y hi/lo
    attn_kernel<<<dim3(T_ / 64, BH_), 128, ASMEM>>>();

    // 4) proj GEMM -> out
    mma_gemm<0><<<dim3(C_ / 128, M_ / 128), 256, GSMEM>>>(yh, yl, wph, wpl,
                                                          b_proj, out, C_);
}

// round 8
// speedup vs baseline: 4.5292x; 1.3490x over previous
#include <cuda_runtime.h>
#include <cuda_bf16.h>
#include <cuda_fp16.h>
#include <math.h>
#include <stdint.h>

// Problem constants
constexpr int B_  = 2;
constexpr int T_  = 2048;
constexpr int C_  = 1024;
constexpr int H_  = 16;
constexpr int HD_ = 64;
constexpr int BH_ = B_ * H_;
constexpr int M_  = B_ * T_;     // 4096
constexpr int K_  = C_;          // 1024
constexpr int NQ_ = 3 * C_;      // 3072

// ---------------------------------------------------------------------------
// Device-global scratch
// ---------------------------------------------------------------------------
__device__ __half g_q[BH_ * T_ * HD_];          // fp16 q/k/v for attention
__device__ __half g_k[BH_ * T_ * HD_];
__device__ __half g_v[BH_ * T_ * HD_];
__device__ __nv_bfloat16 g_yh[M_ * C_],   g_yl[M_ * C_];
__device__ __nv_bfloat16 g_xh[M_ * K_],   g_xl[M_ * K_];
__device__ __nv_bfloat16 g_wah[NQ_ * K_], g_wal[NQ_ * K_];  // W_attn^T [N,K]
__device__ __nv_bfloat16 g_wph[C_ * K_],  g_wpl[C_ * K_];   // W_proj^T [N,K]

// ---------------------------------------------------------------------------
// PTX helpers (baseline ISA features only)
// ---------------------------------------------------------------------------
__device__ __forceinline__ uint32_t su32(const void* p) {
    uint32_t a;
    asm("{ .reg .u64 t; cvta.to.shared.u64 t, %1; cvt.u32.u64 %0, t; }"
        : "=r"(a) : "l"(p));
    return a;
}

__device__ __forceinline__ void ldm_x4(uint32_t* r, uint32_t addr) {
    asm volatile("ldmatrix.sync.aligned.m8n8.x4.shared.b16 {%0,%1,%2,%3}, [%4];"
        : "=r"(r[0]), "=r"(r[1]), "=r"(r[2]), "=r"(r[3]) : "r"(addr));
}

__device__ __forceinline__ void ldm_x4t(uint32_t* r, uint32_t addr) {
    asm volatile("ldmatrix.sync.aligned.m8n8.x4.trans.shared.b16 {%0,%1,%2,%3}, [%4];"
        : "=r"(r[0]), "=r"(r[1]), "=r"(r[2]), "=r"(r[3]) : "r"(addr));
}

__device__ __forceinline__ void mma_bf16(float* d, const uint32_t* a,
                                         const uint32_t* b) {
    asm volatile(
        "mma.sync.aligned.m16n8k16.row.col.f32.bf16.bf16.f32 "
        "{%0,%1,%2,%3}, {%4,%5,%6,%7}, {%8,%9}, {%0,%1,%2,%3};"
        : "+f"(d[0]), "+f"(d[1]), "+f"(d[2]), "+f"(d[3])
        : "r"(a[0]), "r"(a[1]), "r"(a[2]), "r"(a[3]), "r"(b[0]), "r"(b[1]));
}

__device__ __forceinline__ void mma_f16(float* d, const uint32_t* a,
                                        const uint32_t* b) {
    asm volatile(
        "mma.sync.aligned.m16n8k16.row.col.f32.f16.f16.f32 "
        "{%0,%1,%2,%3}, {%4,%5,%6,%7}, {%8,%9}, {%0,%1,%2,%3};"
        : "+f"(d[0]), "+f"(d[1]), "+f"(d[2]), "+f"(d[3])
        : "r"(a[0]), "r"(a[1]), "r"(a[2]), "r"(a[3]), "r"(b[0]), "r"(b[1]));
}

__device__ __forceinline__ void cp16(uint32_t saddr, const void* g) {
    asm volatile("cp.async.cg.shared.global [%0], [%1], 16;"
                 :: "r"(saddr), "l"(g));
}
#define CP_COMMIT() asm volatile("cp.async.commit_group;" ::: "memory")
template<int N> __device__ __forceinline__ void cp_wait() {
    asm volatile("cp.async.wait_group %0;" :: "n"(N) : "memory");
}

__device__ __forceinline__ void split1(float a, __nv_bfloat16& h, __nv_bfloat16& l) {
    h = __float2bfloat16_rn(a);
    l = __float2bfloat16_rn(a - __bfloat162float(h));
}
__device__ __forceinline__ uint32_t pack2h(float a, float b) {
    __half2 t = __floats2half2_rn(a, b);
    return *(uint32_t*)&t;
}

// ---------------------------------------------------------------------------
// Split x -> bf16 hi/lo
// ---------------------------------------------------------------------------
__global__ void __launch_bounds__(256) split_x(const float* __restrict__ src) {
    const int i = blockIdx.x * 256 + threadIdx.x;   // float4 index
    float4 v = ((const float4*)src)[i];
    __nv_bfloat16 h0, h1, h2, h3, l0, l1, l2, l3;
    split1(v.x, h0, l0); split1(v.y, h1, l1);
    split1(v.z, h2, l2); split1(v.w, h3, l3);
    ((__nv_bfloat162*)g_xh)[2 * i]     = __nv_bfloat162(h0, h1);
    ((__nv_bfloat162*)g_xh)[2 * i + 1] = __nv_bfloat162(h2, h3);
    ((__nv_bfloat162*)g_xl)[2 * i]     = __nv_bfloat162(l0, l1);
    ((__nv_bfloat162*)g_xl)[2 * i + 1] = __nv_bfloat162(l2, l3);
}

// Split + transpose weights: W[K,N] fp32 -> Wt[N,K] bf16 hi/lo
template<int DST>
__global__ void __launch_bounds__(256) split_wT(const float* __restrict__ W,
                                                int Kdim, int Ndim) {
    __nv_bfloat16* Th = (DST == 0) ? g_wah : g_wph;
    __nv_bfloat16* Tl = (DST == 0) ? g_wal : g_wpl;
    __shared__ float t[32][33];
    const int n0 = blockIdx.x * 32, k0 = blockIdx.y * 32;
    const int tx = threadIdx.x & 31, ty = threadIdx.x >> 5;
    #pragma unroll
    for (int r = 0; r < 32; r += 8)
        t[ty + r][tx] = W[(size_t)(k0 + ty + r) * Ndim + n0 + tx];
    __syncthreads();
    #pragma unroll
    for (int r = 0; r < 32; r += 8) {
        const int n = n0 + ty + r, k = k0 + tx;
        __nv_bfloat16 h, l;
        split1(t[tx][ty + r], h, l);
        Th[(size_t)n * Kdim + k] = h;
        Tl[(size_t)n * Kdim + k] = l;
    }
}

// ---------------------------------------------------------------------------
// HMMA GEMM: 3-stage cp.async pipeline, ONE barrier per chunk, 2 CTAs/SM.
// 128x128 CTA, BK=32, 8 warps (2x4). 3-term bf16 hi/lo. XOR chunk swizzle.
// EPI=1: QKV scatter (fp16).  EPI=0: fp32 store.
// ---------------------------------------------------------------------------
constexpr int GST    = 32;                 // smem row stride (bf16), no pad
constexpr int GTILE  = 128 * GST;          // bf16 per tile
constexpr int GSTAGE = 4 * GTILE;          // Ah,Al,Bh,Bl
constexpr int GSMEM  = 3 * GSTAGE * 2;     // bytes (3 stages) = 98304
constexpr int GNK    = K_ / 32;            // 32 k-chunks

__device__ __forceinline__ int gswz(int row, int col) {
    return row * GST + ((((col >> 3) ^ ((row >> 1) & 3)) << 3));
}

template<int EPI>
__global__ void __launch_bounds__(256, 2) mma_gemm(
    const __nv_bfloat16* __restrict__ Ah, const __nv_bfloat16* __restrict__ Al,
    const __nv_bfloat16* __restrict__ Bh, const __nv_bfloat16* __restrict__ Bl,
    const float* __restrict__ bias, float* __restrict__ Cout, int N)
{
    extern __shared__ __nv_bfloat16 dsm[];

    const int tid = threadIdx.x;
    const int wid = tid >> 5, lane = tid & 31;
    const int wm = wid >> 2, wn = wid & 3;
    const int m0 = blockIdx.y * 128, n0 = blockIdx.x * 128;

    float acc[4][4][4] = {};

    auto issue = [&](int kt, int stg) {
        const int k0 = kt * 32;
        __nv_bfloat16* s = dsm + stg * GSTAGE;
        #pragma unroll
        for (int it = 0; it < 8; it++) {
            const int idx  = it * 256 + tid;
            const int tile = idx >> 9;
            const int rem  = idx & 511;
            const int row  = rem >> 2;
            const int c8   = (rem & 3) * 8;
            const __nv_bfloat16* gp;
            if      (tile == 0) gp = Ah + (size_t)(m0 + row) * K_ + k0 + c8;
            else if (tile == 1) gp = Al + (size_t)(m0 + row) * K_ + k0 + c8;
            else if (tile == 2) gp = Bh + (size_t)(n0 + row) * K_ + k0 + c8;
            else                gp = Bl + (size_t)(n0 + row) * K_ + k0 + c8;
            cp16(su32(&s[tile * GTILE + gswz(row, c8)]), gp);
        }
    };

    auto compute = [&](int stg) {
        const __nv_bfloat16* sAh = dsm + stg * GSTAGE;
        const __nv_bfloat16* sAl = sAh + GTILE;
        const __nv_bfloat16* sBh = sAl + GTILE;
        const __nv_bfloat16* sBl = sBh + GTILE;
        #pragma unroll
        for (int ks = 0; ks < 2; ks++) {
            uint32_t ah[4][4], al[4][4];
            const int arow = (lane & 15);
            const int acol = ks * 16 + ((lane >> 4) << 3);
            #pragma unroll
            for (int ti = 0; ti < 4; ti++) {
                const int off = gswz(wm * 64 + ti * 16 + arow, acol);
                ldm_x4(ah[ti], su32(&sAh[off]));
                ldm_x4(al[ti], su32(&sAl[off]));
            }
            uint32_t bh4[2][4], bl4[2][4];
            const int brow = (lane & 7) + ((lane >> 4) << 3);
            const int bcol = ks * 16 + (((lane >> 3) & 1) << 3);
            #pragma unroll
            for (int tp = 0; tp < 2; tp++) {
                const int off = gswz(wn * 32 + tp * 16 + brow, bcol);
                ldm_x4(bh4[tp], su32(&sBh[off]));
                ldm_x4(bl4[tp], su32(&sBl[off]));
            }
            #pragma unroll
            for (int ti = 0; ti < 4; ti++)
                #pragma unroll
                for (int tj = 0; tj < 4; tj++) {
                    const uint32_t* bhf = &bh4[tj >> 1][(tj & 1) * 2];
                    const uint32_t* blf = &bl4[tj >> 1][(tj & 1) * 2];
                    mma_bf16(acc[ti][tj], ah[ti], bhf);
                    mma_bf16(acc[ti][tj], ah[ti], blf);
                    mma_bf16(acc[ti][tj], al[ti], bhf);
                }
        }
    };

    issue(0, 0);
    CP_COMMIT();
    issue(1, 1);
    CP_COMMIT();
    #pragma unroll 1
    for (int kt = 0; kt < GNK; kt++) {
        if (kt + 1 < GNK) cp_wait<1>(); else cp_wait<0>();
        __syncthreads();
        compute(kt % 3);
        if (kt + 2 < GNK) {
            issue(kt + 2, (kt + 2) % 3);
            CP_COMMIT();
        }
    }

    // Epilogue
    #pragma unroll
    for (int ti = 0; ti < 4; ti++) {
        #pragma unroll
        for (int tj = 0; tj < 4; tj++) {
            const int n = n0 + wn * 32 + tj * 8 + 2 * (lane & 3);
            const float b0 = bias[n], b1 = bias[n + 1];
            #pragma unroll
            for (int half_ = 0; half_ < 2; half_++) {
                const int m = m0 + wm * 64 + ti * 16 + (lane >> 2) + half_ * 8;
                const float v0 = acc[ti][tj][half_ * 2 + 0] + b0;
                const float v1 = acc[ti][tj][half_ * 2 + 1] + b1;
                if (EPI == 0) {
                    float2* p = (float2*)&Cout[(size_t)m * N + n];
                    *p = make_float2(v0, v1);
                } else {
                    const int sel = n >> 10;
                    const int rr  = n & 1023;
                    const int h   = rr >> 6;
                    const int d   = rr & 63;
                    const int bb  = m >> 11;
                    const int t   = m & 2047;
                    const size_t o = (((size_t)bb * H_ + h) * T_ + t) * HD_ + d;
                    __half* dst = (sel == 0) ? g_q : (sel == 1) ? g_k : g_v;
                    *(__half2*)(dst + o) = __floats2half2_rn(v0, v1);
                }
            }
        }
    }
}

// ---------------------------------------------------------------------------
// Causal flash attention, plain fp16 operands (error ~2^-12, see theory).
// CTA = 64 queries, 4 warps x 16 rows; 64-key tiles, 2-stage cp.async.
// Longest-first CTA scheduling. smem 36KB -> ~6 CTAs/SM.
// ---------------------------------------------------------------------------
constexpr int AST    = 72;               // row stride (half); 144B, 16B-aligned
constexpr int ATILE  = 64 * AST;         // half per tile
constexpr int ASTAGE = 2 * ATILE;        // K,V
constexpr int ASMEM  = 2 * ASTAGE * 2;   // bytes = 36864

__global__ void __launch_bounds__(128) attn_kernel() {
    extern __shared__ __half adsm[];

    const int bh  = blockIdx.y;
    const int q0  = (gridDim.x - 1 - blockIdx.x) * 64;   // longest-first
    const int tid = threadIdx.x, wid = tid >> 5, lane = tid & 31;
    const int NT  = q0 / 64 + 1;

    const size_t base = (size_t)bh * T_ * HD_;
    const __half* __restrict__ qp = g_q + base;
    const __half* __restrict__ kp = g_k + base;
    const __half* __restrict__ vp = g_v + base;

    // Stage Q into stage-0 K area, pull A-fragments, then release.
    #pragma unroll
    for (int rr = 0; rr < 4; rr++) {
        const int idx = rr * 128 + tid;          // 512 uint4 slots
        const int row = idx >> 3, c8 = (idx & 7) * 8;
        *(uint4*)&adsm[row * AST + c8] =
            *(const uint4*)(qp + (size_t)(q0 + row) * HD_ + c8);
    }
    __syncthreads();

    uint32_t qf[4][4];
    {
        const int arow = lane & 15;
        const int ac   = (lane >> 4) << 3;
        #pragma unroll
        for (int dt = 0; dt < 4; dt++) {
            const int off = (wid * 16 + arow) * AST + dt * 16 + ac;
            ldm_x4(qf[dt], su32(&adsm[off]));
        }
    }
    __syncthreads();

    auto issue_kv = [&](int t, int stg) {
        const int k0 = t * 64;
        __half* s = adsm + stg * ASTAGE;
        #pragma unroll
        for (int it = 0; it < 8; it++) {
            const int idx  = it * 128 + tid;         // 1024 uint4 slots
            const int tile = idx >> 9;
            const int rem  = idx & 511;
            const int row  = rem >> 3;
            const int c8   = (rem & 7) * 8;
            const size_t g = (size_t)(k0 + row) * HD_ + c8;
            const __half* gp = (tile == 0) ? (kp + g) : (vp + g);
            cp16(su32(&s[tile * ATILE + row * AST + c8]), gp);
        }
    };

    float of[8][4] = {};
    float m0r = -1e30f, m1r = -1e30f, l0r = 0.f, l1r = 0.f;
    const float scale = 0.03125f;   // 1/sqrt(1024)

    issue_kv(0, 0);
    CP_COMMIT();

    #pragma unroll 1
    for (int t = 0; t < NT; t++) {
        if (t + 1 < NT) {
            issue_kv(t + 1, (t + 1) & 1);
            CP_COMMIT();
            cp_wait<1>();
        } else {
            cp_wait<0>();
        }
        __syncthreads();

        const __half* sK = adsm + (t & 1) * ASTAGE;
        const __half* sV = sK + ATILE;
        const int k0 = t * 64;

        // S = Q K^T (plain fp16)
        float sf[8][4];
        const int krow = lane & 7;
        const int kc   = (lane >> 3) << 3;
        #pragma unroll
        for (int nt = 0; nt < 8; nt++) {
            sf[nt][0] = sf[nt][1] = sf[nt][2] = sf[nt][3] = 0.f;
            uint32_t k0f[4], k1f[4];
            const int off0 = (nt * 8 + krow) * AST + kc;
            ldm_x4(k0f, su32(&sK[off0]));
            ldm_x4(k1f, su32(&sK[off0 + 32]));
            #pragma unroll
            for (int dt = 0; dt < 4; dt++) {
                const uint32_t* kf = (dt < 2) ? &k0f[(dt & 1) * 2] : &k1f[(dt & 1) * 2];
                mma_f16(sf[nt], qf[dt], kf);
            }
        }

        // scale + causal mask (diagonal tile only)
        const int rr0 = wid * 16 + (lane >> 2);
        #pragma unroll
        for (int nt = 0; nt < 8; nt++) {
            #pragma unroll
            for (int e = 0; e < 4; e++) sf[nt][e] *= scale;
        }
        if (k0 == q0) {
            #pragma unroll
            for (int nt = 0; nt < 8; nt++) {
                const int col = nt * 8 + 2 * (lane & 3);
                #pragma unroll
                for (int e = 0; e < 4; e++) {
                    const int c = col + (e & 1);
                    const int r = rr0 + ((e >> 1) << 3);
                    if (c > r) sf[nt][e] = -1e30f;
                }
            }
        }

        // Online softmax stats
        float mt0 = -1e30f, mt1 = -1e30f;
        #pragma unroll
        for (int nt = 0; nt < 8; nt++) {
            mt0 = fmaxf(mt0, fmaxf(sf[nt][0], sf[nt][1]));
            mt1 = fmaxf(mt1, fmaxf(sf[nt][2], sf[nt][3]));
        }
        mt0 = fmaxf(mt0, __shfl_xor_sync(0xffffffff, mt0, 1));
        mt0 = fmaxf(mt0, __shfl_xor_sync(0xffffffff, mt0, 2));
        mt1 = fmaxf(mt1, __shfl_xor_sync(0xffffffff, mt1, 1));
        mt1 = fmaxf(mt1, __shfl_xor_sync(0xffffffff, mt1, 2));

        const float mn0 = fmaxf(m0r, mt0), mn1 = fmaxf(m1r, mt1);
        const float c0 = __expf(m0r - mn0), c1 = __expf(m1r - mn1);

        float ls0 = 0.f, ls1 = 0.f;
        #pragma unroll
        for (int nt = 0; nt < 8; nt++) {
            sf[nt][0] = __expf(sf[nt][0] - mn0);
            sf[nt][1] = __expf(sf[nt][1] - mn0);
            sf[nt][2] = __expf(sf[nt][2] - mn1);
            sf[nt][3] = __expf(sf[nt][3] - mn1);
            ls0 += sf[nt][0] + sf[nt][1];
            ls1 += sf[nt][2] + sf[nt][3];
        }
        ls0 += __shfl_xor_sync(0xffffffff, ls0, 1);
        ls0 += __shfl_xor_sync(0xffffffff, ls0, 2);
        ls1 += __shfl_xor_sync(0xffffffff, ls1, 1);
        ls1 += __shfl_xor_sync(0xffffffff, ls1, 2);

        l0r = l0r * c0 + ls0;
        l1r = l1r * c1 + ls1;
        m0r = mn0; m1r = mn1;

        #pragma unroll
        for (int nt = 0; nt < 8; nt++) {
            of[nt][0] *= c0; of[nt][1] *= c0;
            of[nt][2] *= c1; of[nt][3] *= c1;
        }

        // Pack P into fp16 A-fragments
        uint32_t pf[4][4];
        #pragma unroll
        for (int kt = 0; kt < 4; kt++) {
            #pragma unroll
            for (int q = 0; q < 4; q++) {
                pf[kt][q] = pack2h(sf[2 * kt + (q >> 1)][(q & 1) * 2 + 0],
                                   sf[2 * kt + (q >> 1)][(q & 1) * 2 + 1]);
            }
        }

        // O += P V (plain fp16)
        #pragma unroll
        for (int ntd = 0; ntd < 8; ntd++) {
            uint32_t vha[4], vhb[4];
            ldm_x4t(vha, su32(&sV[(lane)      * AST + ntd * 8]));
            ldm_x4t(vhb, su32(&sV[(32 + lane) * AST + ntd * 8]));
            #pragma unroll
            for (int kt = 0; kt < 4; kt++) {
                const uint32_t* vf = (kt < 2) ? &vha[(kt & 1) * 2] : &vhb[(kt & 1) * 2];
                mma_f16(of[ntd], pf[kt], vf);
            }
        }
        __syncthreads();
    }

    // Normalize + store y as bf16 hi/lo (proj GEMM A operand)
    const float inv0 = 1.f / l0r, inv1 = 1.f / l1r;
    const int b = bh >> 4, h = bh & 15;
    const int row0 = q0 + wid * 16 + (lane >> 2);
    const int dx = 2 * (lane & 3);
    #pragma unroll
    for (int ntd = 0; ntd < 8; ntd++) {
        const int d = h * HD_ + ntd * 8 + dx;
        {
            const float y0 = of[ntd][0] * inv0, y1 = of[ntd][1] * inv0;
            __nv_bfloat16 h0, l0, h1, l1;
            split1(y0, h0, l0); split1(y1, h1, l1);
            const size_t o = ((size_t)b * T_ + row0) * C_ + d;
            *(__nv_bfloat162*)(g_yh + o) = __nv_bfloat162(h0, h1);
            *(__nv_bfloat162*)(g_yl + o) = __nv_bfloat162(l0, l1);
        }
        {
            const float y0 = of[ntd][2] * inv1, y1 = of[ntd][3] * inv1;
            __nv_bfloat16 h0, l0, h1, l1;
            split1(y0, h0, l0); split1(y1, h1, l1);
            const size_t o = ((size_t)b * T_ + row0 + 8) * C_ + d;
            *(__nv_bfloat162*)(g_yh + o) = __nv_bfloat162(h0, h1);
            *(__nv_bfloat162*)(g_yl + o) = __nv_bfloat162(l0, l1);
        }
    }
}

// ---------------------------------------------------------------------------
// Launch
// ---------------------------------------------------------------------------
extern "C" void kernel_launch(void* const* d_in, const int* in_sizes, int n_in,
                              void* d_out, int out_size)
{
    const float* x      = (const float*)d_in[0];
    const float* W_attn = (const float*)d_in[1];
    const float* b_attn = (const float*)d_in[2];
    const float* W_proj = (const float*)d_in[3];
    const float* b_proj = (const float*)d_in[4];
    float* out = (float*)d_out;

    __nv_bfloat16 *xh, *xl, *wah, *wal, *wph, *wpl, *yh, *yl;
    cudaGetSymbolAddress((void**)&xh,  g_xh);
    cudaGetSymbolAddress((void**)&xl,  g_xl);
    cudaGetSymbolAddress((void**)&wah, g_wah);
    cudaGetSymbolAddress((void**)&wal, g_wal);
    cudaGetSymbolAddress((void**)&wph, g_wph);
    cudaGetSymbolAddress((void**)&wpl, g_wpl);
    cudaGetSymbolAddress((void**)&yh,  g_yh);
    cudaGetSymbolAddress((void**)&yl,  g_yl);

    cudaFuncSetAttribute(mma_gemm<1>, cudaFuncAttributeMaxDynamicSharedMemorySize, GSMEM);
    cudaFuncSetAttribute(mma_gemm<0>, cudaFuncAttributeMaxDynamicSharedMemorySize, GSMEM);
    cudaFuncSetAttribute(attn_kernel, cudaFuncAttributeMaxDynamicSharedMemorySize, ASMEM);

    // 1) splits
    split_x<<<(M_ * K_) / 1024, 256>>>(x);
    split_wT<0><<<dim3(NQ_ / 32, K_ / 32), 256>>>(W_attn, K_, NQ_);
    split_wT<1><<<dim3(C_ / 32, K_ / 32), 256>>>(W_proj, K_, C_);

    // 2) QKV GEMM -> q/k/v fp16
    mma_gemm<1><<<dim3(NQ_ / 128, M_ / 128), 256, GSMEM>>>(xh, xl, wah, wal,
                                                           b_attn, nullptr, NQ_);
    // 3) causal attention -> y bf16 hi/lo
    attn_kernel<<<dim3(T_ / 64, BH_), 128, ASMEM>>>();

    // 4) proj GEMM -> out
    mma_gemm<0><<<dim3(C_ / 128, M_ / 128), 256, GSMEM>>>(yh, yl, wph, wpl,
                                                          b_proj, out, C_);
}

// round 9
// speedup vs baseline: 7.3627x; 1.6256x over previous
#include <cuda_runtime.h>
#include <cuda_bf16.h>
#include <cuda_fp16.h>
#include <math.h>
#include <stdint.h>

// Problem constants
constexpr int B_  = 2;
constexpr int T_  = 2048;
constexpr int C_  = 1024;
constexpr int H_  = 16;
constexpr int HD_ = 64;
constexpr int BH_ = B_ * H_;
constexpr int M_  = B_ * T_;     // 4096
constexpr int K_  = C_;          // 1024
constexpr int NQ_ = 3 * C_;      // 3072

// ---------------------------------------------------------------------------
// Device-global scratch (all fp16 now)
// ---------------------------------------------------------------------------
__device__ __half g_q[BH_ * T_ * HD_];
__device__ __half g_k[BH_ * T_ * HD_];
__device__ __half g_v[BH_ * T_ * HD_];
__device__ __half g_y16[M_ * C_];
__device__ __half g_x16[M_ * K_];
__device__ __half g_wa16[NQ_ * K_];   // W_attn^T [N,K]
__device__ __half g_wp16[C_ * K_];    // W_proj^T [N,K]

// ---------------------------------------------------------------------------
// PTX helpers (baseline ISA features only)
// ---------------------------------------------------------------------------
__device__ __forceinline__ uint32_t su32(const void* p) {
    uint32_t a;
    asm("{ .reg .u64 t; cvta.to.shared.u64 t, %1; cvt.u32.u64 %0, t; }"
        : "=r"(a) : "l"(p));
    return a;
}

__device__ __forceinline__ void ldm_x4(uint32_t* r, uint32_t addr) {
    asm volatile("ldmatrix.sync.aligned.m8n8.x4.shared.b16 {%0,%1,%2,%3}, [%4];"
        : "=r"(r[0]), "=r"(r[1]), "=r"(r[2]), "=r"(r[3]) : "r"(addr));
}

__device__ __forceinline__ void ldm_x4t(uint32_t* r, uint32_t addr) {
    asm volatile("ldmatrix.sync.aligned.m8n8.x4.trans.shared.b16 {%0,%1,%2,%3}, [%4];"
        : "=r"(r[0]), "=r"(r[1]), "=r"(r[2]), "=r"(r[3]) : "r"(addr));
}

__device__ __forceinline__ void mma_f16(float* d, const uint32_t* a,
                                        const uint32_t* b) {
    asm volatile(
        "mma.sync.aligned.m16n8k16.row.col.f32.f16.f16.f32 "
        "{%0,%1,%2,%3}, {%4,%5,%6,%7}, {%8,%9}, {%0,%1,%2,%3};"
        : "+f"(d[0]), "+f"(d[1]), "+f"(d[2]), "+f"(d[3])
        : "r"(a[0]), "r"(a[1]), "r"(a[2]), "r"(a[3]), "r"(b[0]), "r"(b[1]));
}

__device__ __forceinline__ void cp16(uint32_t saddr, const void* g) {
    asm volatile("cp.async.cg.shared.global [%0], [%1], 16;"
                 :: "r"(saddr), "l"(g));
}
#define CP_COMMIT() asm volatile("cp.async.commit_group;" ::: "memory")
template<int N> __device__ __forceinline__ void cp_wait() {
    asm volatile("cp.async.wait_group %0;" :: "n"(N) : "memory");
}

__device__ __forceinline__ uint32_t pack2h(float a, float b) {
    __half2 t = __floats2half2_rn(a, b);
    return *(uint32_t*)&t;
}

// ---------------------------------------------------------------------------
// Convert x -> fp16
// ---------------------------------------------------------------------------
__global__ void __launch_bounds__(256) conv_x(const float* __restrict__ src) {
    const int i = blockIdx.x * 256 + threadIdx.x;   // float4 index
    float4 v = ((const float4*)src)[i];
    ((__half2*)g_x16)[2 * i]     = __floats2half2_rn(v.x, v.y);
    ((__half2*)g_x16)[2 * i + 1] = __floats2half2_rn(v.z, v.w);
}

// Transpose + convert weights: W[K,N] fp32 -> Wt[N,K] fp16
template<int DST>
__global__ void __launch_bounds__(256) conv_wT(const float* __restrict__ W,
                                               int Kdim, int Ndim) {
    __half* Tt = (DST == 0) ? g_wa16 : g_wp16;
    __shared__ float t[32][33];
    const int n0 = blockIdx.x * 32, k0 = blockIdx.y * 32;
    const int tx = threadIdx.x & 31, ty = threadIdx.x >> 5;
    #pragma unroll
    for (int r = 0; r < 32; r += 8)
        t[ty + r][tx] = W[(size_t)(k0 + ty + r) * Ndim + n0 + tx];
    __syncthreads();
    #pragma unroll
    for (int r = 0; r < 32; r += 8) {
        const int n = n0 + ty + r, k = k0 + tx;
        Tt[(size_t)n * Kdim + k] = __float2half_rn(t[tx][ty + r]);
    }
}

// ---------------------------------------------------------------------------
// fp16 HMMA GEMM: 3-stage cp.async pipeline, ONE barrier per chunk,
// 2 CTAs/SM. 128x128 CTA, BK=32, 8 warps (2x4). XOR chunk swizzle.
// EPI=1: QKV scatter (fp16).  EPI=0: fp32 store.
// ---------------------------------------------------------------------------
constexpr int GST    = 32;                 // smem row stride (half), no pad
constexpr int GTILE  = 128 * GST;          // half per tile
constexpr int GSTAGE = 2 * GTILE;          // A, B
constexpr int GSMEM  = 3 * GSTAGE * 2;     // bytes (3 stages) = 49152
constexpr int GNK    = K_ / 32;            // 32 k-chunks

__device__ __forceinline__ int gswz(int row, int col) {
    return row * GST + ((((col >> 3) ^ ((row >> 1) & 3)) << 3));
}

template<int EPI>
__global__ void __launch_bounds__(256, 2) mma_gemm(
    const __half* __restrict__ A, const __half* __restrict__ Bm,
    const float* __restrict__ bias, float* __restrict__ Cout, int N)
{
    extern __shared__ __half dsm[];

    const int tid = threadIdx.x;
    const int wid = tid >> 5, lane = tid & 31;
    const int wm = wid >> 2, wn = wid & 3;
    const int m0 = blockIdx.y * 128, n0 = blockIdx.x * 128;

    float acc[4][4][4] = {};

    // stage issue: 2 tiles x 128 rows x 4 uint4 = 1024 cp16, 4/thread
    auto issue = [&](int kt, int stg) {
        const int k0 = kt * 32;
        __half* s = dsm + stg * GSTAGE;
        #pragma unroll
        for (int it = 0; it < 4; it++) {
            const int idx  = it * 256 + tid;
            const int tile = idx >> 9;
            const int rem  = idx & 511;
            const int row  = rem >> 2;
            const int c8   = (rem & 3) * 8;
            const __half* gp = (tile == 0)
                ? A  + (size_t)(m0 + row) * K_ + k0 + c8
                : Bm + (size_t)(n0 + row) * K_ + k0 + c8;
            cp16(su32(&s[tile * GTILE + gswz(row, c8)]), gp);
        }
    };

    auto compute = [&](int stg) {
        const __half* sA = dsm + stg * GSTAGE;
        const __half* sB = sA + GTILE;
        #pragma unroll
        for (int ks = 0; ks < 2; ks++) {
            uint32_t af[4][4];
            const int arow = (lane & 15);
            const int acol = ks * 16 + ((lane >> 4) << 3);
            #pragma unroll
            for (int ti = 0; ti < 4; ti++)
                ldm_x4(af[ti], su32(&sA[gswz(wm * 64 + ti * 16 + arow, acol)]));
            uint32_t bf4[2][4];
            const int brow = (lane & 7) + ((lane >> 4) << 3);
            const int bcol = ks * 16 + (((lane >> 3) & 1) << 3);
            #pragma unroll
            for (int tp = 0; tp < 2; tp++)
                ldm_x4(bf4[tp], su32(&sB[gswz(wn * 32 + tp * 16 + brow, bcol)]));
            #pragma unroll
            for (int ti = 0; ti < 4; ti++)
                #pragma unroll
                for (int tj = 0; tj < 4; tj++)
                    mma_f16(acc[ti][tj], af[ti], &bf4[tj >> 1][(tj & 1) * 2]);
        }
    };

    issue(0, 0);
    CP_COMMIT();
    issue(1, 1);
    CP_COMMIT();
    #pragma unroll 1
    for (int kt = 0; kt < GNK; kt++) {
        if (kt + 1 < GNK) cp_wait<1>(); else cp_wait<0>();
        __syncthreads();
        compute(kt % 3);
        if (kt + 2 < GNK) {
            issue(kt + 2, (kt + 2) % 3);
            CP_COMMIT();
        }
    }

    // Epilogue
    #pragma unroll
    for (int ti = 0; ti < 4; ti++) {
        #pragma unroll
        for (int tj = 0; tj < 4; tj++) {
            const int n = n0 + wn * 32 + tj * 8 + 2 * (lane & 3);
            const float b0 = bias[n], b1 = bias[n + 1];
            #pragma unroll
            for (int half_ = 0; half_ < 2; half_++) {
                const int m = m0 + wm * 64 + ti * 16 + (lane >> 2) + half_ * 8;
                const float v0 = acc[ti][tj][half_ * 2 + 0] + b0;
                const float v1 = acc[ti][tj][half_ * 2 + 1] + b1;
                if (EPI == 0) {
                    float2* p = (float2*)&Cout[(size_t)m * N + n];
                    *p = make_float2(v0, v1);
                } else {
                    const int sel = n >> 10;
                    const int rr  = n & 1023;
                    const int h   = rr >> 6;
                    const int d   = rr & 63;
                    const int bb  = m >> 11;
                    const int t   = m & 2047;
                    const size_t o = (((size_t)bb * H_ + h) * T_ + t) * HD_ + d;
                    __half* dst = (sel == 0) ? g_q : (sel == 1) ? g_k : g_v;
                    *(__half2*)(dst + o) = __floats2half2_rn(v0, v1);
                }
            }
        }
    }
}

// ---------------------------------------------------------------------------
// Causal flash attention, plain fp16 operands.
// CTA = 64 queries, 4 warps x 16 rows; 64-key tiles, 2-stage cp.async.
// Longest-first CTA scheduling. smem 36KB.
// ---------------------------------------------------------------------------
constexpr int AST    = 72;               // row stride (half); 144B, 16B-aligned
constexpr int ATILE  = 64 * AST;         // half per tile
constexpr int ASTAGE = 2 * ATILE;        // K,V
constexpr int ASMEM  = 2 * ASTAGE * 2;   // bytes = 36864

__global__ void __launch_bounds__(128) attn_kernel() {
    extern __shared__ __half adsm[];

    const int bh  = blockIdx.y;
    const int q0  = (gridDim.x - 1 - blockIdx.x) * 64;   // longest-first
    const int tid = threadIdx.x, wid = tid >> 5, lane = tid & 31;
    const int NT  = q0 / 64 + 1;

    const size_t base = (size_t)bh * T_ * HD_;
    const __half* __restrict__ qp = g_q + base;
    const __half* __restrict__ kp = g_k + base;
    const __half* __restrict__ vp = g_v + base;

    // Stage Q into stage-0 K area, pull A-fragments, then release.
    #pragma unroll
    for (int rr = 0; rr < 4; rr++) {
        const int idx = rr * 128 + tid;          // 512 uint4 slots
        const int row = idx >> 3, c8 = (idx & 7) * 8;
        *(uint4*)&adsm[row * AST + c8] =
            *(const uint4*)(qp + (size_t)(q0 + row) * HD_ + c8);
    }
    __syncthreads();

    uint32_t qf[4][4];
    {
        const int arow = lane & 15;
        const int ac   = (lane >> 4) << 3;
        #pragma unroll
        for (int dt = 0; dt < 4; dt++) {
            const int off = (wid * 16 + arow) * AST + dt * 16 + ac;
            ldm_x4(qf[dt], su32(&adsm[off]));
        }
    }
    __syncthreads();

    auto issue_kv = [&](int t, int stg) {
        const int k0 = t * 64;
        __half* s = adsm + stg * ASTAGE;
        #pragma unroll
        for (int it = 0; it < 8; it++) {
            const int idx  = it * 128 + tid;         // 1024 uint4 slots
            const int tile = idx >> 9;
            const int rem  = idx & 511;
            const int row  = rem >> 3;
            const int c8   = (rem & 7) * 8;
            const size_t g = (size_t)(k0 + row) * HD_ + c8;
            const __half* gp = (tile == 0) ? (kp + g) : (vp + g);
            cp16(su32(&s[tile * ATILE + row * AST + c8]), gp);
        }
    };

    float of[8][4] = {};
    float m0r = -1e30f, m1r = -1e30f, l0r = 0.f, l1r = 0.f;
    const float scale = 0.03125f;   // 1/sqrt(1024)

    issue_kv(0, 0);
    CP_COMMIT();

    #pragma unroll 1
    for (int t = 0; t < NT; t++) {
        if (t + 1 < NT) {
            issue_kv(t + 1, (t + 1) & 1);
            CP_COMMIT();
            cp_wait<1>();
        } else {
            cp_wait<0>();
        }
        __syncthreads();

        const __half* sK = adsm + (t & 1) * ASTAGE;
        const __half* sV = sK + ATILE;
        const int k0 = t * 64;

        // S = Q K^T
        float sf[8][4];
        const int krow = lane & 7;
        const int kc   = (lane >> 3) << 3;
        #pragma unroll
        for (int nt = 0; nt < 8; nt++) {
            sf[nt][0] = sf[nt][1] = sf[nt][2] = sf[nt][3] = 0.f;
            uint32_t k0f[4], k1f[4];
            const int off0 = (nt * 8 + krow) * AST + kc;
            ldm_x4(k0f, su32(&sK[off0]));
            ldm_x4(k1f, su32(&sK[off0 + 32]));
            #pragma unroll
            for (int dt = 0; dt < 4; dt++) {
                const uint32_t* kf = (dt < 2) ? &k0f[(dt & 1) * 2] : &k1f[(dt & 1) * 2];
                mma_f16(sf[nt], qf[dt], kf);
            }
        }

        // scale + causal mask (diagonal tile only)
        const int rr0 = wid * 16 + (lane >> 2);
        #pragma unroll
        for (int nt = 0; nt < 8; nt++) {
            #pragma unroll
            for (int e = 0; e < 4; e++) sf[nt][e] *= scale;
        }
        if (k0 == q0) {
            #pragma unroll
            for (int nt = 0; nt < 8; nt++) {
                const int col = nt * 8 + 2 * (lane & 3);
                #pragma unroll
                for (int e = 0; e < 4; e++) {
                    const int c = col + (e & 1);
                    const int r = rr0 + ((e >> 1) << 3);
                    if (c > r) sf[nt][e] = -1e30f;
                }
            }
        }

        // Online softmax stats
        float mt0 = -1e30f, mt1 = -1e30f;
        #pragma unroll
        for (int nt = 0; nt < 8; nt++) {
            mt0 = fmaxf(mt0, fmaxf(sf[nt][0], sf[nt][1]));
            mt1 = fmaxf(mt1, fmaxf(sf[nt][2], sf[nt][3]));
        }
        mt0 = fmaxf(mt0, __shfl_xor_sync(0xffffffff, mt0, 1));
        mt0 = fmaxf(mt0, __shfl_xor_sync(0xffffffff, mt0, 2));
        mt1 = fmaxf(mt1, __shfl_xor_sync(0xffffffff, mt1, 1));
        mt1 = fmaxf(mt1, __shfl_xor_sync(0xffffffff, mt1, 2));

        const float mn0 = fmaxf(m0r, mt0), mn1 = fmaxf(m1r, mt1);
        const float c0 = __expf(m0r - mn0), c1 = __expf(m1r - mn1);

        float ls0 = 0.f, ls1 = 0.f;
        #pragma unroll
        for (int nt = 0; nt < 8; nt++) {
            sf[nt][0] = __expf(sf[nt][0] - mn0);
            sf[nt][1] = __expf(sf[nt][1] - mn0);
            sf[nt][2] = __expf(sf[nt][2] - mn1);
            sf[nt][3] = __expf(sf[nt][3] - mn1);
            ls0 += sf[nt][0] + sf[nt][1];
            ls1 += sf[nt][2] + sf[nt][3];
        }
        ls0 += __shfl_xor_sync(0xffffffff, ls0, 1);
        ls0 += __shfl_xor_sync(0xffffffff, ls0, 2);
        ls1 += __shfl_xor_sync(0xffffffff, ls1, 1);
        ls1 += __shfl_xor_sync(0xffffffff, ls1, 2);

        l0r = l0r * c0 + ls0;
        l1r = l1r * c1 + ls1;
        m0r = mn0; m1r = mn1;

        #pragma unroll
        for (int nt = 0; nt < 8; nt++) {
            of[nt][0] *= c0; of[nt][1] *= c0;
            of[nt][2] *= c1; of[nt][3] *= c1;
        }

        // Pack P into fp16 A-fragments
        uint32_t pf[4][4];
        #pragma unroll
        for (int kt = 0; kt < 4; kt++) {
            #pragma unroll
            for (int q = 0; q < 4; q++) {
                pf[kt][q] = pack2h(sf[2 * kt + (q >> 1)][(q & 1) * 2 + 0],
                                   sf[2 * kt + (q >> 1)][(q & 1) * 2 + 1]);
            }
        }

        // O += P V
        #pragma unroll
        for (int ntd = 0; ntd < 8; ntd++) {
            uint32_t vha[4], vhb[4];
            ldm_x4t(vha, su32(&sV[(lane)      * AST + ntd * 8]));
            ldm_x4t(vhb, su32(&sV[(32 + lane) * AST + ntd * 8]));
            #pragma unroll
            for (int kt = 0; kt < 4; kt++) {
                const uint32_t* vf = (kt < 2) ? &vha[(kt & 1) * 2] : &vhb[(kt & 1) * 2];
                mma_f16(of[ntd], pf[kt], vf);
            }
        }
        __syncthreads();
    }

    // Normalize + store y fp16 (proj GEMM A operand)
    const float inv0 = 1.f / l0r, inv1 = 1.f / l1r;
    const int b = bh >> 4, h = bh & 15;
    const int row0 = q0 + wid * 16 + (lane >> 2);
    const int dx = 2 * (lane & 3);
    #pragma unroll
    for (int ntd = 0; ntd < 8; ntd++) {
        const int d = h * HD_ + ntd * 8 + dx;
        {
            const size_t o = ((size_t)b * T_ + row0) * C_ + d;
            *(__half2*)(g_y16 + o) =
                __floats2half2_rn(of[ntd][0] * inv0, of[ntd][1] * inv0);
        }
        {
            const size_t o = ((size_t)b * T_ + row0 + 8) * C_ + d;
            *(__half2*)(g_y16 + o) =
                __floats2half2_rn(of[ntd][2] * inv1, of[ntd][3] * inv1);
        }
    }
}

// ---------------------------------------------------------------------------
// Launch
// ---------------------------------------------------------------------------
extern "C" void kernel_launch(void* const* d_in, const int* in_sizes, int n_in,
                              void* d_out, int out_size)
{
    const float* x      = (const float*)d_in[0];
    const float* W_attn = (const float*)d_in[1];
    const float* b_attn = (const float*)d_in[2];
    const float* W_proj = (const float*)d_in[3];
    const float* b_proj = (const float*)d_in[4];
    float* out = (float*)d_out;

    __half *x16, *wa16, *wp16, *y16;
    cudaGetSymbolAddress((void**)&x16,  g_x16);
    cudaGetSymbolAddress((void**)&wa16, g_wa16);
    cudaGetSymbolAddress((void**)&wp16, g_wp16);
    cudaGetSymbolAddress((void**)&y16,  g_y16);

    cudaFuncSetAttribute(mma_gemm<1>, cudaFuncAttributeMaxDynamicSharedMemorySize, GSMEM);
    cudaFuncSetAttribute(mma_gemm<0>, cudaFuncAttributeMaxDynamicSharedMemorySize, GSMEM);
    cudaFuncSetAttribute(attn_kernel, cudaFuncAttributeMaxDynamicSharedMemorySize, ASMEM);

    // 1) converts
    conv_x<<<(M_ * K_) / 1024, 256>>>(x);
    conv_wT<0><<<dim3(NQ_ / 32, K_ / 32), 256>>>(W_attn, K_, NQ_);
    conv_wT<1><<<dim3(C_ / 32, K_ / 32), 256>>>(W_proj, K_, C_);

    // 2) QKV GEMM -> q/k/v fp16
    mma_gemm<1><<<dim3(NQ_ / 128, M_ / 128), 256, GSMEM>>>(x16, wa16,
                                                           b_attn, nullptr, NQ_);
    // 3) causal attention -> y fp16
    attn_kernel<<<dim3(T_ / 64, BH_), 128, ASMEM>>>();

    // 4) proj GEMM -> out (fp32)
    mma_gemm<0><<<dim3(C_ / 128, M_ / 128), 256, GSMEM>>>(y16, wp16,
                                                          b_proj, out, C_);
}

// round 10
// speedup vs baseline: 7.5414x; 1.0243x over previous
#include <cuda_runtime.h>
#include <cuda_bf16.h>
#include <cuda_fp16.h>
#include <math.h>
#include <stdint.h>

// Problem constants
constexpr int B_  = 2;
constexpr int T_  = 2048;
constexpr int C_  = 1024;
constexpr int H_  = 16;
constexpr int HD_ = 64;
constexpr int BH_ = B_ * H_;
constexpr int M_  = B_ * T_;     // 4096
constexpr int K_  = C_;          // 1024
constexpr int NQ_ = 3 * C_;      // 3072

// ---------------------------------------------------------------------------
// Device-global scratch (all fp16)
// ---------------------------------------------------------------------------
__device__ __half g_q[BH_ * T_ * HD_];
__device__ __half g_k[BH_ * T_ * HD_];
__device__ __half g_v[BH_ * T_ * HD_];
__device__ __half g_y16[M_ * C_];
__device__ __half g_x16[M_ * K_];
__device__ __half g_wa16[NQ_ * K_];   // W_attn^T [N,K]
__device__ __half g_wp16[C_ * K_];    // W_proj^T [N,K]

// ---------------------------------------------------------------------------
// PTX helpers (baseline ISA features only)
// ---------------------------------------------------------------------------
__device__ __forceinline__ uint32_t su32(const void* p) {
    uint32_t a;
    asm("{ .reg .u64 t; cvta.to.shared.u64 t, %1; cvt.u32.u64 %0, t; }"
        : "=r"(a) : "l"(p));
    return a;
}

__device__ __forceinline__ void ldm_x4(uint32_t* r, uint32_t addr) {
    asm volatile("ldmatrix.sync.aligned.m8n8.x4.shared.b16 {%0,%1,%2,%3}, [%4];"
        : "=r"(r[0]), "=r"(r[1]), "=r"(r[2]), "=r"(r[3]) : "r"(addr));
}

__device__ __forceinline__ void ldm_x4t(uint32_t* r, uint32_t addr) {
    asm volatile("ldmatrix.sync.aligned.m8n8.x4.trans.shared.b16 {%0,%1,%2,%3}, [%4];"
        : "=r"(r[0]), "=r"(r[1]), "=r"(r[2]), "=r"(r[3]) : "r"(addr));
}

__device__ __forceinline__ void mma_f16(float* d, const uint32_t* a,
                                        const uint32_t* b) {
    asm volatile(
        "mma.sync.aligned.m16n8k16.row.col.f32.f16.f16.f32 "
        "{%0,%1,%2,%3}, {%4,%5,%6,%7}, {%8,%9}, {%0,%1,%2,%3};"
        : "+f"(d[0]), "+f"(d[1]), "+f"(d[2]), "+f"(d[3])
        : "r"(a[0]), "r"(a[1]), "r"(a[2]), "r"(a[3]), "r"(b[0]), "r"(b[1]));
}

__device__ __forceinline__ void cp16(uint32_t saddr, const void* g) {
    asm volatile("cp.async.cg.shared.global [%0], [%1], 16;"
                 :: "r"(saddr), "l"(g));
}
#define CP_COMMIT() asm volatile("cp.async.commit_group;" ::: "memory")
template<int N> __device__ __forceinline__ void cp_wait() {
    asm volatile("cp.async.wait_group %0;" :: "n"(N) : "memory");
}

__device__ __forceinline__ uint32_t pack2h(float a, float b) {
    __half2 t = __floats2half2_rn(a, b);
    return *(uint32_t*)&t;
}

// ---------------------------------------------------------------------------
// Convert x -> fp16
// ---------------------------------------------------------------------------
__global__ void __launch_bounds__(256) conv_x(const float* __restrict__ src) {
    const int i = blockIdx.x * 256 + threadIdx.x;   // float4 index
    float4 v = ((const float4*)src)[i];
    ((__half2*)g_x16)[2 * i]     = __floats2half2_rn(v.x, v.y);
    ((__half2*)g_x16)[2 * i + 1] = __floats2half2_rn(v.z, v.w);
}

// Transpose + convert weights: W[K,N] fp32 -> Wt[N,K] fp16
template<int DST>
__global__ void __launch_bounds__(256) conv_wT(const float* __restrict__ W,
                                               int Kdim, int Ndim) {
    __half* Tt = (DST == 0) ? g_wa16 : g_wp16;
    __shared__ float t[32][33];
    const int n0 = blockIdx.x * 32, k0 = blockIdx.y * 32;
    const int tx = threadIdx.x & 31, ty = threadIdx.x >> 5;
    #pragma unroll
    for (int r = 0; r < 32; r += 8)
        t[ty + r][tx] = W[(size_t)(k0 + ty + r) * Ndim + n0 + tx];
    __syncthreads();
    #pragma unroll
    for (int r = 0; r < 32; r += 8) {
        const int n = n0 + ty + r, k = k0 + tx;
        Tt[(size_t)n * Kdim + k] = __float2half_rn(t[tx][ty + r]);
    }
}

// ---------------------------------------------------------------------------
// fp16 HMMA GEMM: BK=64, 3-stage cp.async pipeline, ONE barrier per chunk,
// 2 CTAs/SM (96KB smem/CTA). 128x128 CTA, 8 warps (2x4).
// Full SW128 swizzle: chunk' = chunk ^ (row & 7), row = 128B.
// EPI=1: QKV scatter (fp16).  EPI=0: fp32 store.
// ---------------------------------------------------------------------------
constexpr int GST    = 64;                 // smem row stride (half) = 128B
constexpr int GTILE  = 128 * GST;          // half per tile (8192)
constexpr int GSTAGE = 2 * GTILE;          // A, B
constexpr int GSMEM  = 3 * GSTAGE * 2;     // bytes (3 stages) = 98304
constexpr int GNK    = K_ / 64;            // 16 k-chunks

__device__ __forceinline__ int gswz(int row, int col) {
    return row * GST + ((((col >> 3) ^ (row & 7)) << 3));
}

template<int EPI>
__global__ void __launch_bounds__(256, 2) mma_gemm(
    const __half* __restrict__ A, const __half* __restrict__ Bm,
    const float* __restrict__ bias, float* __restrict__ Cout, int N)
{
    extern __shared__ __half dsm[];

    const int tid = threadIdx.x;
    const int wid = tid >> 5, lane = tid & 31;
    const int wm = wid >> 2, wn = wid & 3;
    const int m0 = blockIdx.y * 128, n0 = blockIdx.x * 128;

    float acc[4][4][4] = {};

    // stage issue: 2 tiles x 128 rows x 8 uint4 = 2048 cp16, 8/thread
    auto issue = [&](int kt, int stg) {
        const int k0 = kt * 64;
        __half* s = dsm + stg * GSTAGE;
        #pragma unroll
        for (int it = 0; it < 8; it++) {
            const int idx  = it * 256 + tid;
            const int tile = idx >> 10;
            const int rem  = idx & 1023;
            const int row  = rem >> 3;
            const int c8   = (rem & 7) * 8;
            const __half* gp = (tile == 0)
                ? A  + (size_t)(m0 + row) * K_ + k0 + c8
                : Bm + (size_t)(n0 + row) * K_ + k0 + c8;
            cp16(su32(&s[tile * GTILE + gswz(row, c8)]), gp);
        }
    };

    auto compute = [&](int stg) {
        const __half* sA = dsm + stg * GSTAGE;
        const __half* sB = sA + GTILE;
        #pragma unroll
        for (int ks = 0; ks < 4; ks++) {
            uint32_t af[4][4];
            const int arow = (lane & 15);
            const int acol = ks * 16 + ((lane >> 4) << 3);
            #pragma unroll
            for (int ti = 0; ti < 4; ti++)
                ldm_x4(af[ti], su32(&sA[gswz(wm * 64 + ti * 16 + arow, acol)]));
            uint32_t bf4[2][4];
            const int brow = (lane & 7) + ((lane >> 4) << 3);
            const int bcol = ks * 16 + (((lane >> 3) & 1) << 3);
            #pragma unroll
            for (int tp = 0; tp < 2; tp++)
                ldm_x4(bf4[tp], su32(&sB[gswz(wn * 32 + tp * 16 + brow, bcol)]));
            #pragma unroll
            for (int ti = 0; ti < 4; ti++)
                #pragma unroll
                for (int tj = 0; tj < 4; tj++)
                    mma_f16(acc[ti][tj], af[ti], &bf4[tj >> 1][(tj & 1) * 2]);
        }
    };

    // 3-stage pipeline, depth-2 prefetch, single barrier per chunk.
    issue(0, 0);
    CP_COMMIT();
    issue(1, 1);
    CP_COMMIT();
    #pragma unroll 1
    for (int kt = 0; kt < GNK; kt++) {
        if (kt + 1 < GNK) cp_wait<1>(); else cp_wait<0>();
        __syncthreads();
        compute(kt % 3);
        if (kt + 2 < GNK) {
            issue(kt + 2, (kt + 2) % 3);
            CP_COMMIT();
        }
    }

    // Epilogue
    #pragma unroll
    for (int ti = 0; ti < 4; ti++) {
        #pragma unroll
        for (int tj = 0; tj < 4; tj++) {
            const int n = n0 + wn * 32 + tj * 8 + 2 * (lane & 3);
            const float b0 = bias[n], b1 = bias[n + 1];
            #pragma unroll
            for (int half_ = 0; half_ < 2; half_++) {
                const int m = m0 + wm * 64 + ti * 16 + (lane >> 2) + half_ * 8;
                const float v0 = acc[ti][tj][half_ * 2 + 0] + b0;
                const float v1 = acc[ti][tj][half_ * 2 + 1] + b1;
                if (EPI == 0) {
                    float2* p = (float2*)&Cout[(size_t)m * N + n];
                    *p = make_float2(v0, v1);
                } else {
                    const int sel = n >> 10;
                    const int rr  = n & 1023;
                    const int h   = rr >> 6;
                    const int d   = rr & 63;
                    const int bb  = m >> 11;
                    const int t   = m & 2047;
                    const size_t o = (((size_t)bb * H_ + h) * T_ + t) * HD_ + d;
                    __half* dst = (sel == 0) ? g_q : (sel == 1) ? g_k : g_v;
                    *(__half2*)(dst + o) = __floats2half2_rn(v0, v1);
                }
            }
        }
    }
}

// ---------------------------------------------------------------------------
// Causal flash attention, plain fp16 operands (unchanged from R9).
// CTA = 64 queries, 4 warps x 16 rows; 64-key tiles, 2-stage cp.async.
// Longest-first CTA scheduling. smem 36KB.
// ---------------------------------------------------------------------------
constexpr int AST    = 72;               // row stride (half); 144B, 16B-aligned
constexpr int ATILE  = 64 * AST;         // half per tile
constexpr int ASTAGE = 2 * ATILE;        // K,V
constexpr int ASMEM  = 2 * ASTAGE * 2;   // bytes = 36864

__global__ void __launch_bounds__(128) attn_kernel() {
    extern __shared__ __half adsm[];

    const int bh  = blockIdx.y;
    const int q0  = (gridDim.x - 1 - blockIdx.x) * 64;   // longest-first
    const int tid = threadIdx.x, wid = tid >> 5, lane = tid & 31;
    const int NT  = q0 / 64 + 1;

    const size_t base = (size_t)bh * T_ * HD_;
    const __half* __restrict__ qp = g_q + base;
    const __half* __restrict__ kp = g_k + base;
    const __half* __restrict__ vp = g_v + base;

    // Stage Q into stage-0 K area, pull A-fragments, then release.
    #pragma unroll
    for (int rr = 0; rr < 4; rr++) {
        const int idx = rr * 128 + tid;          // 512 uint4 slots
        const int row = idx >> 3, c8 = (idx & 7) * 8;
        *(uint4*)&adsm[row * AST + c8] =
            *(const uint4*)(qp + (size_t)(q0 + row) * HD_ + c8);
    }
    __syncthreads();

    uint32_t qf[4][4];
    {
        const int arow = lane & 15;
        const int ac   = (lane >> 4) << 3;
        #pragma unroll
        for (int dt = 0; dt < 4; dt++) {
            const int off = (wid * 16 + arow) * AST + dt * 16 + ac;
            ldm_x4(qf[dt], su32(&adsm[off]));
        }
    }
    __syncthreads();

    auto issue_kv = [&](int t, int stg) {
        const int k0 = t * 64;
        __half* s = adsm + stg * ASTAGE;
        #pragma unroll
        for (int it = 0; it < 8; it++) {
            const int idx  = it * 128 + tid;         // 1024 uint4 slots
            const int tile = idx >> 9;
            const int rem  = idx & 511;
            const int row  = rem >> 3;
            const int c8   = (rem & 7) * 8;
            const size_t g = (size_t)(k0 + row) * HD_ + c8;
            const __half* gp = (tile == 0) ? (kp + g) : (vp + g);
            cp16(su32(&s[tile * ATILE + row * AST + c8]), gp);
        }
    };

    float of[8][4] = {};
    float m0r = -1e30f, m1r = -1e30f, l0r = 0.f, l1r = 0.f;
    const float scale = 0.03125f;   // 1/sqrt(1024)

    issue_kv(0, 0);
    CP_COMMIT();

    #pragma unroll 1
    for (int t = 0; t < NT; t++) {
        if (t + 1 < NT) {
            issue_kv(t + 1, (t + 1) & 1);
            CP_COMMIT();
            cp_wait<1>();
        } else {
            cp_wait<0>();
        }
        __syncthreads();

        const __half* sK = adsm + (t & 1) * ASTAGE;
        const __half* sV = sK + ATILE;
        const int k0 = t * 64;

        // S = Q K^T
        float sf[8][4];
        const int krow = lane & 7;
        const int kc   = (lane >> 3) << 3;
        #pragma unroll
        for (int nt = 0; nt < 8; nt++) {
            sf[nt][0] = sf[nt][1] = sf[nt][2] = sf[nt][3] = 0.f;
            uint32_t k0f[4], k1f[4];
            const int off0 = (nt * 8 + krow) * AST + kc;
            ldm_x4(k0f, su32(&sK[off0]));
            ldm_x4(k1f, su32(&sK[off0 + 32]));
            #pragma unroll
            for (int dt = 0; dt < 4; dt++) {
                const uint32_t* kf = (dt < 2) ? &k0f[(dt & 1) * 2] : &k1f[(dt & 1) * 2];
                mma_f16(sf[nt], qf[dt], kf);
            }
        }

        // scale + causal mask (diagonal tile only)
        const int rr0 = wid * 16 + (lane >> 2);
        #pragma unroll
        for (int nt = 0; nt < 8; nt++) {
            #pragma unroll
            for (int e = 0; e < 4; e++) sf[nt][e] *= scale;
        }
        if (k0 == q0) {
            #pragma unroll
            for (int nt = 0; nt < 8; nt++) {
                const int col = nt * 8 + 2 * (lane & 3);
                #pragma unroll
                for (int e = 0; e < 4; e++) {
                    const int c = col + (e & 1);
                    const int r = rr0 + ((e >> 1) << 3);
                    if (c > r) sf[nt][e] = -1e30f;
                }
            }
        }

        // Online softmax stats
        float mt0 = -1e30f, mt1 = -1e30f;
        #pragma unroll
        for (int nt = 0; nt < 8; nt++) {
            mt0 = fmaxf(mt0, fmaxf(sf[nt][0], sf[nt][1]));
            mt1 = fmaxf(mt1, fmaxf(sf[nt][2], sf[nt][3]));
        }
        mt0 = fmaxf(mt0, __shfl_xor_sync(0xffffffff, mt0, 1));
        mt0 = fmaxf(mt0, __shfl_xor_sync(0xffffffff, mt0, 2));
        mt1 = fmaxf(mt1, __shfl_xor_sync(0xffffffff, mt1, 1));
        mt1 = fmaxf(mt1, __shfl_xor_sync(0xffffffff, mt1, 2));

        const float mn0 = fmaxf(m0r, mt0), mn1 = fmaxf(m1r, mt1);
        const float c0 = __expf(m0r - mn0), c1 = __expf(m1r - mn1);

        float ls0 = 0.f, ls1 = 0.f;
        #pragma unroll
        for (int nt = 0; nt < 8; nt++) {
            sf[nt][0] = __expf(sf[nt][0] - mn0);
            sf[nt][1] = __expf(sf[nt][1] - mn0);
            sf[nt][2] = __expf(sf[nt][2] - mn1);
            sf[nt][3] = __expf(sf[nt][3] - mn1);
            ls0 += sf[nt][0] + sf[nt][1];
            ls1 += sf[nt][2] + sf[nt][3];
        }
        ls0 += __shfl_xor_sync(0xffffffff, ls0, 1);
        ls0 += __shfl_xor_sync(0xffffffff, ls0, 2);
        ls1 += __shfl_xor_sync(0xffffffff, ls1, 1);
        ls1 += __shfl_xor_sync(0xffffffff, ls1, 2);

        l0r = l0r * c0 + ls0;
        l1r = l1r * c1 + ls1;
        m0r = mn0; m1r = mn1;

        #pragma unroll
        for (int nt = 0; nt < 8; nt++) {
            of[nt][0] *= c0; of[nt][1] *= c0;
            of[nt][2] *= c1; of[nt][3] *= c1;
        }

        // Pack P into fp16 A-fragments
        uint32_t pf[4][4];
        #pragma unroll
        for (int kt = 0; kt < 4; kt++) {
            #pragma unroll
            for (int q = 0; q < 4; q++) {
                pf[kt][q] = pack2h(sf[2 * kt + (q >> 1)][(q & 1) * 2 + 0],
                                   sf[2 * kt + (q >> 1)][(q & 1) * 2 + 1]);
            }
        }

        // O += P V
        #pragma unroll
        for (int ntd = 0; ntd < 8; ntd++) {
            uint32_t vha[4], vhb[4];
            ldm_x4t(vha, su32(&sV[(lane)      * AST + ntd * 8]));
            ldm_x4t(vhb, su32(&sV[(32 + lane) * AST + ntd * 8]));
            #pragma unroll
            for (int kt = 0; kt < 4; kt++) {
                const uint32_t* vf = (kt < 2) ? &vha[(kt & 1) * 2] : &vhb[(kt & 1) * 2];
                mma_f16(of[ntd], pf[kt], vf);
            }
        }
        __syncthreads();
    }

    // Normalize + store y fp16 (proj GEMM A operand)
    const float inv0 = 1.f / l0r, inv1 = 1.f / l1r;
    const int b = bh >> 4, h = bh & 15;
    const int row0 = q0 + wid * 16 + (lane >> 2);
    const int dx = 2 * (lane & 3);
    #pragma unroll
    for (int ntd = 0; ntd < 8; ntd++) {
        const int d = h * HD_ + ntd * 8 + dx;
        {
            const size_t o = ((size_t)b * T_ + row0) * C_ + d;
            *(__half2*)(g_y16 + o) =
                __floats2half2_rn(of[ntd][0] * inv0, of[ntd][1] * inv0);
        }
        {
            const size_t o = ((size_t)b * T_ + row0 + 8) * C_ + d;
            *(__half2*)(g_y16 + o) =
                __floats2half2_rn(of[ntd][2] * inv1, of[ntd][3] * inv1);
        }
    }
}

// ---------------------------------------------------------------------------
// Launch
// ---------------------------------------------------------------------------
extern "C" void kernel_launch(void* const* d_in, const int* in_sizes, int n_in,
                              void* d_out, int out_size)
{
    const float* x      = (const float*)d_in[0];
    const float* W_attn = (const float*)d_in[1];
    const float* b_attn = (const float*)d_in[2];
    const float* W_proj = (const float*)d_in[3];
    const float* b_proj = (const float*)d_in[4];
    float* out = (float*)d_out;

    __half *x16, *wa16, *wp16, *y16;
    cudaGetSymbolAddress((void**)&x16,  g_x16);
    cudaGetSymbolAddress((void**)&wa16, g_wa16);
    cudaGetSymbolAddress((void**)&wp16, g_wp16);
    cudaGetSymbolAddress((void**)&y16,  g_y16);

    cudaFuncSetAttribute(mma_gemm<1>, cudaFuncAttributeMaxDynamicSharedMemorySize, GSMEM);
    cudaFuncSetAttribute(mma_gemm<0>, cudaFuncAttributeMaxDynamicSharedMemorySize, GSMEM);
    cudaFuncSetAttribute(attn_kernel, cudaFuncAttributeMaxDynamicSharedMemorySize, ASMEM);

    // 1) converts
    conv_x<<<(M_ * K_) / 1024, 256>>>(x);
    conv_wT<0><<<dim3(NQ_ / 32, K_ / 32), 256>>>(W_attn, K_, NQ_);
    conv_wT<1><<<dim3(C_ / 32, K_ / 32), 256>>>(W_proj, K_, C_);

    // 2) QKV GEMM -> q/k/v fp16
    mma_gemm<1><<<dim3(NQ_ / 128, M_ / 128), 256, GSMEM>>>(x16, wa16,
                                                           b_attn, nullptr, NQ_);
    // 3) causal attention -> y fp16
    attn_kernel<<<dim3(T_ / 64, BH_), 128, ASMEM>>>();

    // 4) proj GEMM -> out (fp32)
    mma_gemm<0><<<dim3(C_ / 128, M_ / 128), 256, GSMEM>>>(y16, wp16,
                                                          b_proj, out, C_);
}